// round 11
// baseline (speedup 1.0000x reference)
#include <cuda_runtime.h>
#include <cuda_fp16.h>
#include <cstdint>

// Problem constants
#define N_TOK 4096
#define H_DIM 2048
#define I_DIM 1408
#define N_EXP 8
#define CAP   1280   // int(1.25 * (2*N/E))

// Pipeline: CTA 128(m) x 256(B-rows), 16 warps 4m x 4n, warp 32x64, k-chunk 64
#define NSTAGE  4
#define STAGE_B 49152          // bytes/stage: A 128x64 fp16 = 16KB, B 256x64 fp16 = 32KB
#define B_OFF   16384
#define NTHR    512

// ----------------------------- scratch (static device globals) -------------
__device__ int   g_top2idx[2 * N_TOK];
__device__ float g_top2val[2 * N_TOK];
__device__ int   g_tokens[N_EXP * CAP];
__device__ float g_wts[N_EXP * CAP];
__device__ int   g_slot[2 * N_TOK];
__device__ int   g_counts[N_EXP];
__device__ __align__(256) __half g_Xh [(size_t)N_TOK * H_DIM];             // x fp16 permuted
__device__ __align__(256) __half g_Wgu[(size_t)N_EXP * 2 * I_DIM * H_DIM]; // interleaved g/u rows
__device__ __align__(256) __half g_Wdh[(size_t)N_EXP * H_DIM * I_DIM];     // Wd fp16 permuted
__device__ __align__(256) __half g_Ph [(size_t)N_EXP * CAP * I_DIM];       // swiglu out (fp16, permuted)
__device__ __align__(256) __half g_O  [(size_t)N_EXP * CAP * H_DIM];       // per-slot down output (fp16)

// ----------------------------- helpers -------------------------------------
__device__ __forceinline__ uint32_t smem_u32(const void* p) {
    uint32_t a;
    asm("{ .reg .u64 t; cvta.to.shared.u64 t, %1; cvt.u32.u64 %0, t; }"
        : "=r"(a) : "l"(p));
    return a;
}
// fragment-contiguous permutation within a 32-elem (64B) k-block:
// thread t4 owns fp16 positions [t4*8, t4*8+8) = {c0:k=2t4,2t4+1,2t4+8,2t4+9; c1:+16}
__device__ __forceinline__ int perm32(int j) {
    int kk = j & 15;
    return ((kk >> 1) & 3) * 8 + (j >> 4) * 4 + (kk >> 3) * 2 + (kk & 1);
}
__device__ __forceinline__ void cpa16(uint32_t dst, const void* src) {
    asm volatile("cp.async.cg.shared.global [%0], [%1], 16;" :: "r"(dst), "l"(src));
}
__device__ __forceinline__ void cpa_commit() {
    asm volatile("cp.async.commit_group;" ::: "memory");
}
__device__ __forceinline__ void cpa_wait2() {
    asm volatile("cp.async.wait_group 2;" ::: "memory");
}
__device__ __forceinline__ void mma_f16(float* c, uint32_t a0, uint32_t a1,
                                        uint32_t a2, uint32_t a3,
                                        uint32_t b0, uint32_t b1) {
    asm volatile(
        "mma.sync.aligned.m16n8k16.row.col.f32.f16.f16.f32 "
        "{%0,%1,%2,%3}, {%4,%5,%6,%7}, {%8,%9}, {%0,%1,%2,%3};"
        : "+f"(c[0]), "+f"(c[1]), "+f"(c[2]), "+f"(c[3])
        : "r"(a0), "r"(a1), "r"(a2), "r"(a3), "r"(b0), "r"(b1));
}
// pack 32 fp32 -> 32 fp16 with perm32 layout, write as 4x uint4 (64B)
__device__ __forceinline__ void pack32(const float* v, uint4* dst) {
    unsigned short h[32];
#pragma unroll
    for (int j = 0; j < 32; j++)
        h[perm32(j)] = __half_as_ushort(__float2half_rn(v[j]));
    unsigned w[16];
#pragma unroll
    for (int i = 0; i < 16; i++)
        w[i] = (unsigned)h[2 * i] | ((unsigned)h[2 * i + 1] << 16);
    dst[0] = make_uint4(w[0],  w[1],  w[2],  w[3]);
    dst[1] = make_uint4(w[4],  w[5],  w[6],  w[7]);
    dst[2] = make_uint4(w[8],  w[9],  w[10], w[11]);
    dst[3] = make_uint4(w[12], w[13], w[14], w[15]);
}

// ----------------------------- router --------------------------------------
__global__ void router_kernel(const float* __restrict__ x, const float* __restrict__ Wr) {
    const int warp = threadIdx.x >> 5;
    const int lane = threadIdx.x & 31;
    const int n = blockIdx.x * 8 + warp;

    const float4* xr = reinterpret_cast<const float4*>(x) + (size_t)n * (H_DIM / 4);
    const float4* wr = reinterpret_cast<const float4*>(Wr);

    float acc[N_EXP];
#pragma unroll
    for (int e = 0; e < N_EXP; e++) acc[e] = 0.f;

    for (int i = lane; i < H_DIM / 4; i += 32) {
        float4 xv = xr[i];
#pragma unroll
        for (int e = 0; e < N_EXP; e++) {
            float4 wv = wr[e * (H_DIM / 4) + i];
            acc[e] += xv.x * wv.x + xv.y * wv.y + xv.z * wv.z + xv.w * wv.w;
        }
    }
#pragma unroll
    for (int off = 16; off > 0; off >>= 1) {
#pragma unroll
        for (int e = 0; e < N_EXP; e++)
            acc[e] += __shfl_xor_sync(0xffffffffu, acc[e], off);
    }

    if (lane == 0) {
        float m = acc[0];
#pragma unroll
        for (int e = 1; e < N_EXP; e++) m = fmaxf(m, acc[e]);
        float ex[N_EXP];
        float s = 0.f;
#pragma unroll
        for (int e = 0; e < N_EXP; e++) { ex[e] = __expf(acc[e] - m); s += ex[e]; }
        float inv = 1.f / s;

        float v1 = -1.f; int i1 = 0;
#pragma unroll
        for (int e = 0; e < N_EXP; e++) if (ex[e] > v1) { v1 = ex[e]; i1 = e; }
        float v2 = -1.f; int i2 = 0;
#pragma unroll
        for (int e = 0; e < N_EXP; e++) if (e != i1 && ex[e] > v2) { v2 = ex[e]; i2 = e; }

        g_top2idx[n]         = i1;
        g_top2idx[N_TOK + n] = i2;
        g_top2val[n]         = v1 * inv;
        g_top2val[N_TOK + n] = v2 * inv;
    }
}

// ----------------------------- capacity scheduler ---------------------------
__global__ void sched_kernel() {
    const int tid  = threadIdx.x;           // 0..1023
    const int lane = tid & 31;
    const int wid  = tid >> 5;

    for (int i = tid; i < N_EXP * CAP; i += 1024) {
        g_tokens[i] = 0;
        g_wts[i] = 0.f;
    }

    int   e_loc[8];
    float v_loc[8];
    unsigned pk[4] = {0u, 0u, 0u, 0u};
#pragma unroll
    for (int j = 0; j < 8; j++) {
        int p = tid * 8 + j;
        int e = g_top2idx[p];
        e_loc[j] = e;
        v_loc[j] = g_top2val[p];
        pk[e >> 1] += 1u << ((e & 1) * 16);
    }
    unsigned own[4] = {pk[0], pk[1], pk[2], pk[3]};

#pragma unroll
    for (int off = 1; off < 32; off <<= 1) {
#pragma unroll
        for (int w = 0; w < 4; w++) {
            unsigned u = __shfl_up_sync(0xffffffffu, pk[w], off);
            if (lane >= off) pk[w] += u;
        }
    }

    __shared__ unsigned wsum[32][4];
    if (lane == 31) {
#pragma unroll
        for (int w = 0; w < 4; w++) wsum[wid][w] = pk[w];
    }
    __syncthreads();
    if (wid == 0) {
        unsigned q[4];
#pragma unroll
        for (int w = 0; w < 4; w++) q[w] = wsum[lane][w];
#pragma unroll
        for (int off = 1; off < 32; off <<= 1) {
#pragma unroll
            for (int w = 0; w < 4; w++) {
                unsigned u = __shfl_up_sync(0xffffffffu, q[w], off);
                if (lane >= off) q[w] += u;
            }
        }
#pragma unroll
        for (int w = 0; w < 4; w++) wsum[lane][w] = q[w];
    }
    __syncthreads();

    int off8[8];
#pragma unroll
    for (int w = 0; w < 4; w++) {
        unsigned ex = pk[w] - own[w] + (wid ? wsum[wid - 1][w] : 0u);
        off8[2 * w]     = (int)(ex & 0xFFFFu);
        off8[2 * w + 1] = (int)(ex >> 16);
    }

#pragma unroll
    for (int j = 0; j < 8; j++) {
        int e = e_loc[j];
        int r = off8[e]++;
        int p = tid * 8 + j;
        if (r < CAP) {
            g_tokens[e * CAP + r] = p & (N_TOK - 1);
            g_wts[e * CAP + r]    = v_loc[j];
            g_slot[p] = e * CAP + r;
        } else {
            g_slot[p] = -1;
        }
    }

    if (tid == 0) {
#pragma unroll
        for (int e = 0; e < N_EXP; e++) {
            unsigned u = wsum[31][e >> 1];
            unsigned tot = (e & 1) ? (u >> 16) : (u & 0xFFFFu);
            g_counts[e] = (tot > CAP) ? CAP : (int)tot;
        }
    }
}

// ----------------------------- fp16 prep (vectorized, coalesced) ------------
__global__ void prep_x(const float* __restrict__ x) {
    const int t = blockIdx.x * 256 + threadIdx.x;      // over N_TOK*H/32 blocks
    const float4* src = reinterpret_cast<const float4*>(x) + (size_t)t * 8;
    float v[32];
#pragma unroll
    for (int i = 0; i < 8; i++) {
        float4 f = src[i];
        v[i * 4] = f.x; v[i * 4 + 1] = f.y; v[i * 4 + 2] = f.z; v[i * 4 + 3] = f.w;
    }
    pack32(v, reinterpret_cast<uint4*>(g_Xh) + (size_t)t * 4);
}
// split: blockIdx.y = 0 -> gate rows (2i), 1 -> up rows (2i+1); ei_base = expert-half offset
__global__ void prep_wgu(const float* __restrict__ Wg, const float* __restrict__ Wu, int ei_base) {
    const int t = blockIdx.x * 256 + threadIdx.x;      // over (E/2)*I*(H/32)
    const int kb = t & 63;                              // H/32 = 64
    const int ei = (t >> 6) + ei_base;                  // e*I + i
    const int e  = ei / I_DIM;
    const int i  = ei - e * I_DIM;
    const int y  = blockIdx.y;
    const float* W = y ? Wu : Wg;
    const size_t srcb = (size_t)ei * (H_DIM / 4) + kb * 8;
    const size_t dstb = ((size_t)e * 2 * I_DIM + 2 * i + y) * (H_DIM / 8) + kb * 4;
    float v[32];
    const float4* sw = reinterpret_cast<const float4*>(W) + srcb;
#pragma unroll
    for (int q = 0; q < 8; q++) {
        float4 f = sw[q];
        v[q * 4] = f.x; v[q * 4 + 1] = f.y; v[q * 4 + 2] = f.z; v[q * 4 + 3] = f.w;
    }
    pack32(v, reinterpret_cast<uint4*>(g_Wgu) + dstb);
}
__global__ void prep_wd(const float* __restrict__ Wd) {
    const int t = blockIdx.x * 256 + threadIdx.x;      // over E*H*(I/32)
    const int kb  = t % 44;                             // I/32 = 44
    const int row = t / 44;
    const float4* src = reinterpret_cast<const float4*>(Wd) + (size_t)row * (I_DIM / 4) + kb * 8;
    float v[32];
#pragma unroll
    for (int q = 0; q < 8; q++) {
        float4 f = src[q];
        v[q * 4] = f.x; v[q * 4 + 1] = f.y; v[q * 4 + 2] = f.z; v[q * 4 + 3] = f.w;
    }
    pack32(v, reinterpret_cast<uint4*>(g_Wdh) + (size_t)row * (I_DIM / 8) + kb * 4);
}

// ----------------------------- gate+up GEMM + SwiGLU ------------------------
// B tile 256 rows = 128 I-cols, rows 2i/2i+1 = Wg/Wu (prebuilt in g_Wgu).
// 16 warps 4m x 4n, warp tile 32(m) x 64(B-rows). Epilogue staged via smem.
__global__ __launch_bounds__(NTHR, 1)
void gu_kernel(int e_base) {
    const int e  = e_base + blockIdx.z;
    const int m0 = blockIdx.x * 128;
    const int by = blockIdx.y;                   // I block (128 cols)
    const int n0 = by * 128;
    if (m0 >= g_counts[e]) return;

    extern __shared__ char sm[];
    const uint32_t sbase = smem_u32(sm);

    const int tid  = threadIdx.x;
    const int wid  = tid >> 5;
    const int lane = tid & 31;
    const int g    = lane >> 2;
    const int t4   = lane & 3;
    const int wm   = (wid >> 2) * 32;
    const int wn   = (wid & 3) * 64;
    const int gp   = g & 1;                      // row parity of fragment rows

    // loaders: 512 threads; r = tid>>3 (0..63), slice s (16B) of 128B row-chunk
    const int r  = tid >> 3;
    const int s  = tid & 7;
    const int rp = r & 1;                        // parity same for r, r+64, r+128, r+192
    const uint32_t sl = ((s >> 2) ^ rp) * 64 + (s & 3) * 16;  // swizzled 16B slot

    const char* srcA[2]; uint32_t dA[2];
    const char* srcB[4]; uint32_t dB[4];
#pragma unroll
    for (int j = 0; j < 2; j++) {
        int row = r + j * 64;
        srcA[j] = (const char*)(g_Xh + (size_t)g_tokens[e * CAP + m0 + row] * H_DIM) + s * 16;
        dA[j] = (uint32_t)(row * 128) + sl;
    }
#pragma unroll
    for (int j = 0; j < 4; j++) {
        int row = r + j * 64;
        srcB[j] = (const char*)(g_Wgu + ((size_t)e * 2 * I_DIM + (size_t)by * 256 + row) * H_DIM) + s * 16;
        dB[j] = (uint32_t)(B_OFF + row * 128) + sl;
    }

    auto LOAD = [&](int c, int buf) {
        const uint32_t b = sbase + buf * STAGE_B;
        const size_t off = (size_t)c * 128;
#pragma unroll
        for (int j = 0; j < 2; j++) cpa16(b + dA[j], srcA[j] + off);
#pragma unroll
        for (int j = 0; j < 4; j++) cpa16(b + dB[j], srcB[j] + off);
    };

    float acc[2][8][4];
#pragma unroll
    for (int mt = 0; mt < 2; mt++)
#pragma unroll
        for (int nt = 0; nt < 8; nt++)
#pragma unroll
            for (int qq = 0; qq < 4; qq++) acc[mt][nt][qq] = 0.f;

    const int KT = H_DIM / 64;   // 32
    LOAD(0, 0); cpa_commit();
    LOAD(1, 1); cpa_commit();
    LOAD(2, 2); cpa_commit();

#pragma unroll 1
    for (int c = 0; c < KT; c++) {
        cpa_wait2();
        __syncthreads();
        if (c + 3 < KT) LOAD(c + 3, (c + 3) & 3);
        cpa_commit();

        const char* st = sm + (c & 3) * STAGE_B;
#pragma unroll
        for (int ks = 0; ks < 2; ks++) {
            const int col = (ks ^ gp) * 64 + t4 * 16;
            uint4 aLo[2], aHi[2];
#pragma unroll
            for (int mt = 0; mt < 2; mt++) {
                const int row = wm + mt * 16 + g;
                aLo[mt] = *reinterpret_cast<const uint4*>(st + row * 128 + col);
                aHi[mt] = *reinterpret_cast<const uint4*>(st + (row + 8) * 128 + col);
            }
#pragma unroll
            for (int nt = 0; nt < 8; nt++) {
                const int row = wn + nt * 8 + g;
                uint4 bv = *reinterpret_cast<const uint4*>(st + B_OFF + row * 128 + col);
#pragma unroll
                for (int mt = 0; mt < 2; mt++)
                    mma_f16(acc[mt][nt], aLo[mt].x, aHi[mt].x, aLo[mt].y, aHi[mt].y, bv.x, bv.y);
#pragma unroll
                for (int mt = 0; mt < 2; mt++)
                    mma_f16(acc[mt][nt], aLo[mt].z, aHi[mt].z, aLo[mt].w, aHi[mt].w, bv.z, bv.w);
            }
        }
    }

    // ---- epilogue: stage P tile in smem, then coalesced write-out ----
    __syncthreads();
    __half* Ps = reinterpret_cast<__half*>(sm);
    const int PSTR = 136;                        // halves per row (272B stride)
#pragma unroll
    for (int mt = 0; mt < 2; mt++) {
        const int r0 = wm + mt * 16 + g;
#pragma unroll
        for (int nt = 0; nt < 8; nt++) {
            const int ic  = (wn >> 1) + nt * 4 + t4;      // local I col 0..127
            const int pos = (ic & ~31) + perm32(ic & 31); // even for even ic
            float gv0 = acc[mt][nt][0], uv0 = acc[mt][nt][1];
            float v0 = gv0 * uv0 / (1.f + __expf(-gv0));
            float gv1 = acc[mt][nt][2], uv1 = acc[mt][nt][3];
            float v1 = gv1 * uv1 / (1.f + __expf(-gv1));
            uint32_t h0 = (uint32_t)__half_as_ushort(__float2half_rn(v0));
            uint32_t h1 = (uint32_t)__half_as_ushort(__float2half_rn(v1));
            uint32_t p0 = __shfl_xor_sync(0xffffffffu, h0, 1);
            uint32_t p1 = __shfl_xor_sync(0xffffffffu, h1, 1);
            if ((t4 & 1) == 0) {
                *reinterpret_cast<uint32_t*>(&Ps[r0 * PSTR + pos])       = h0 | (p0 << 16);
                *reinterpret_cast<uint32_t*>(&Ps[(r0 + 8) * PSTR + pos]) = h1 | (p1 << 16);
            }
        }
    }
    __syncthreads();
    {
        const int rr = tid >> 2, part = tid & 3;   // 128 rows x 4 segments of 64B
        const uint4* srcp = reinterpret_cast<const uint4*>(Ps + rr * PSTR + part * 32);
        uint4* dstp = reinterpret_cast<uint4*>(
            g_Ph + ((size_t)e * CAP + m0 + rr) * I_DIM + n0 + part * 32);
#pragma unroll
        for (int q = 0; q < 4; q++) dstp[q] = srcp[q];
    }
}

// ----------------------------- down GEMM ------------------------------------
// 128 x 256(H) tile; A = g_Ph (fp16 permuted), B = g_Wdh. 16 warps 4m x 4n.
// Epilogue staged via smem -> coalesced fp16 g_O.
__global__ __launch_bounds__(NTHR, 1)
void down_kernel() {
    const int e  = blockIdx.z;
    const int m0 = blockIdx.x * 128;
    const int n0 = blockIdx.y * 256;
    if (m0 >= g_counts[e]) return;

    extern __shared__ char sm[];
    const uint32_t sbase = smem_u32(sm);

    const int tid  = threadIdx.x;
    const int wid  = tid >> 5;
    const int lane = tid & 31;
    const int g    = lane >> 2;
    const int t4   = lane & 3;
    const int wm   = (wid >> 2) * 32;
    const int wn   = (wid & 3) * 64;
    const int gp   = g & 1;

    const int r  = tid >> 3;
    const int s  = tid & 7;
    const int rp = r & 1;
    const uint32_t sl = ((s >> 2) ^ rp) * 64 + (s & 3) * 16;

    const char* srcA[2]; uint32_t dA[2];
    const char* srcB[4]; uint32_t dB[4];
#pragma unroll
    for (int j = 0; j < 2; j++) {
        int row = r + j * 64;
        srcA[j] = (const char*)(g_Ph + ((size_t)e * CAP + m0 + row) * I_DIM) + s * 16;
        dA[j] = (uint32_t)(row * 128) + sl;
    }
#pragma unroll
    for (int j = 0; j < 4; j++) {
        int row = r + j * 64;
        srcB[j] = (const char*)(g_Wdh + ((size_t)e * H_DIM + n0 + row) * I_DIM) + s * 16;
        dB[j] = (uint32_t)(B_OFF + row * 128) + sl;
    }

    auto LOAD = [&](int c, int buf) {
        const uint32_t b = sbase + buf * STAGE_B;
        const size_t off = (size_t)c * 128;
#pragma unroll
        for (int j = 0; j < 2; j++) cpa16(b + dA[j], srcA[j] + off);
#pragma unroll
        for (int j = 0; j < 4; j++) cpa16(b + dB[j], srcB[j] + off);
    };

    float acc[2][8][4];
#pragma unroll
    for (int mt = 0; mt < 2; mt++)
#pragma unroll
        for (int nt = 0; nt < 8; nt++)
#pragma unroll
            for (int qq = 0; qq < 4; qq++) acc[mt][nt][qq] = 0.f;

    const int KT = I_DIM / 64;   // 22
    LOAD(0, 0); cpa_commit();
    LOAD(1, 1); cpa_commit();
    LOAD(2, 2); cpa_commit();

#pragma unroll 1
    for (int c = 0; c < KT; c++) {
        cpa_wait2();
        __syncthreads();
        if (c + 3 < KT) LOAD(c + 3, (c + 3) & 3);
        cpa_commit();

        const char* st = sm + (c & 3) * STAGE_B;
#pragma unroll
        for (int ks = 0; ks < 2; ks++) {
            const int col = (ks ^ gp) * 64 + t4 * 16;
            uint4 aLo[2], aHi[2];
#pragma unroll
            for (int mt = 0; mt < 2; mt++) {
                const int row = wm + mt * 16 + g;
                aLo[mt] = *reinterpret_cast<const uint4*>(st + row * 128 + col);
                aHi[mt] = *reinterpret_cast<const uint4*>(st + (row + 8) * 128 + col);
            }
#pragma unroll
            for (int nt = 0; nt < 8; nt++) {
                const int row = wn + nt * 8 + g;
                uint4 bv = *reinterpret_cast<const uint4*>(st + B_OFF + row * 128 + col);
#pragma unroll
                for (int mt = 0; mt < 2; mt++)
                    mma_f16(acc[mt][nt], aLo[mt].x, aHi[mt].x, aLo[mt].y, aHi[mt].y, bv.x, bv.y);
#pragma unroll
                for (int mt = 0; mt < 2; mt++)
                    mma_f16(acc[mt][nt], aLo[mt].z, aHi[mt].z, aLo[mt].w, aHi[mt].w, bv.z, bv.w);
            }
        }
    }

    // ---- epilogue: stage O tile (128x256 fp16) in smem, coalesced write ----
    __syncthreads();
    __half* Os = reinterpret_cast<__half*>(sm);
    const int OSTR = 264;                        // halves per row (528B stride)
#pragma unroll
    for (int mt = 0; mt < 2; mt++) {
        const int r0 = wm + mt * 16 + g;
#pragma unroll
        for (int nt = 0; nt < 8; nt++) {
            const int cc = wn + nt * 8 + t4 * 2;
            *reinterpret_cast<__half2*>(&Os[r0 * OSTR + cc]) =
                __floats2half2_rn(acc[mt][nt][0], acc[mt][nt][1]);
            *reinterpret_cast<__half2*>(&Os[(r0 + 8) * OSTR + cc]) =
                __floats2half2_rn(acc[mt][nt][2], acc[mt][nt][3]);
        }
    }
    __syncthreads();
    {
        const int rr = tid & 127, part = tid >> 7;   // 128 rows x 4 segments of 128B
        const uint4* srcp = reinterpret_cast<const uint4*>(Os + rr * OSTR + part * 64);
        uint4* dstp = reinterpret_cast<uint4*>(
            g_O + ((size_t)e * CAP + m0 + rr) * H_DIM + n0 + part * 64);
#pragma unroll
        for (int q = 0; q < 8; q++) dstp[q] = srcp[q];
    }
}

// ----------------------------- combine --------------------------------------
__global__ void combine_kernel(float* __restrict__ out) {
    const int idx = blockIdx.x * 256 + threadIdx.x;  // over N_TOK * H_DIM/4
    const int n  = idx >> 9;                         // H_DIM/4 = 512
    const int c2 = (idx & 511) * 2;                  // half2 index within row
    const int s0 = g_slot[n];
    const int s1 = g_slot[N_TOK + n];
    float4 acc = make_float4(0.f, 0.f, 0.f, 0.f);
    const __half2* O2 = reinterpret_cast<const __half2*>(g_O);
    if (s0 >= 0) {
        float w = g_wts[s0];
        float2 a = __half22float2(O2[(size_t)s0 * (H_DIM / 2) + c2]);
        float2 b = __half22float2(O2[(size_t)s0 * (H_DIM / 2) + c2 + 1]);
        acc.x += w * a.x; acc.y += w * a.y; acc.z += w * b.x; acc.w += w * b.y;
    }
    if (s1 >= 0) {
        float w = g_wts[s1];
        float2 a = __half22float2(O2[(size_t)s1 * (H_DIM / 2) + c2]);
        float2 b = __half22float2(O2[(size_t)s1 * (H_DIM / 2) + c2 + 1]);
        acc.x += w * a.x; acc.y += w * a.y; acc.z += w * b.x; acc.w += w * b.y;
    }
    reinterpret_cast<float4*>(out)[idx] = acc;
}

// ----------------------------- launch --------------------------------------
#define DYN_SMEM (NSTAGE * STAGE_B)   // 196608 bytes

extern "C" void kernel_launch(void* const* d_in, const int* in_sizes, int n_in,
                              void* d_out, int out_size) {
    const float* x  = (const float*)d_in[0];
    const float* Wr = (const float*)d_in[1];
    const float* Wg = (const float*)d_in[2];
    const float* Wu = (const float*)d_in[3];
    const float* Wd = (const float*)d_in[4];
    float* out = (float*)d_out;
    (void)in_sizes; (void)n_in; (void)out_size;

    // side streams + events for fork-join graph (host resources, created once)
    static cudaStream_t s1 = nullptr, s2 = nullptr;
    static cudaEvent_t evr = nullptr, ev1a = nullptr, ev1b = nullptr,
                       ev2 = nullptr, evx = nullptr;
    if (s1 == nullptr) {
        cudaStreamCreateWithFlags(&s1, cudaStreamNonBlocking);
        cudaStreamCreateWithFlags(&s2, cudaStreamNonBlocking);
        cudaEventCreateWithFlags(&evr, cudaEventDisableTiming);
        cudaEventCreateWithFlags(&ev1a, cudaEventDisableTiming);
        cudaEventCreateWithFlags(&ev1b, cudaEventDisableTiming);
        cudaEventCreateWithFlags(&ev2, cudaEventDisableTiming);
        cudaEventCreateWithFlags(&evx, cudaEventDisableTiming);
    }
    cudaFuncSetAttribute(gu_kernel,   cudaFuncAttributeMaxDynamicSharedMemorySize, DYN_SMEM);
    cudaFuncSetAttribute(down_kernel, cudaFuncAttributeMaxDynamicSharedMemorySize, DYN_SMEM);

    // fork
    cudaEventRecord(evr, 0);
    cudaStreamWaitEvent(s1, evr, 0);
    cudaStreamWaitEvent(s2, evr, 0);

    // chain A (main stream): routing
    router_kernel<<<N_TOK / 8, 256>>>(x, Wr);
    sched_kernel<<<1, 1024>>>();

    // chain B (s1): gate/up weights in two expert-halves (gu half1 starts early)
    const int WGU_HALF_BLKS = ((N_EXP / 2) * I_DIM * (H_DIM / 32)) / 256;  // 1408
    dim3 wgrid(WGU_HALF_BLKS, 2);
    prep_wgu<<<wgrid, 256, 0, s1>>>(Wg, Wu, 0);
    cudaEventRecord(ev1a, s1);
    prep_wgu<<<wgrid, 256, 0, s1>>>(Wg, Wu, (N_EXP / 2) * I_DIM);
    cudaEventRecord(ev1b, s1);

    // chain C (s2): activations first (gu needs them), then down weights
    prep_x  <<<(N_TOK * H_DIM / 32) / 256, 256, 0, s2>>>(x);
    cudaEventRecord(evx, s2);
    prep_wd <<<(N_EXP * H_DIM * (I_DIM / 32)) / 256, 256, 0, s2>>>(Wd);
    cudaEventRecord(ev2, s2);

    // join (wgu-half1, x) -> gu experts 0-3; half2 prep overlaps gu half1
    cudaStreamWaitEvent(0, ev1a, 0);
    cudaStreamWaitEvent(0, evx, 0);
    dim3 ggrid(CAP / 128, I_DIM / 128, N_EXP / 2);   // (10, 11, 4)
    gu_kernel<<<ggrid, NTHR, DYN_SMEM>>>(0);
    cudaStreamWaitEvent(0, ev1b, 0);
    gu_kernel<<<ggrid, NTHR, DYN_SMEM>>>(N_EXP / 2);

    // join wd -> down (prep_wd hides under gu)
    cudaStreamWaitEvent(0, ev2, 0);
    dim3 dgrid(CAP / 128, H_DIM / 256, N_EXP);   // (10, 8, 8)
    down_kernel<<<dgrid, NTHR, DYN_SMEM>>>();

    combine_kernel<<<(N_TOK * (H_DIM / 4)) / 256, 256>>>(out);
}

// round 12
// speedup vs baseline: 1.0684x; 1.0684x over previous
#include <cuda_runtime.h>
#include <cuda_fp16.h>
#include <cstdint>

// Problem constants
#define N_TOK 4096
#define H_DIM 2048
#define I_DIM 1408
#define N_EXP 8
#define CAP   1280   // int(1.25 * (2*N/E))

// Pipeline: CTA 128(m) x 256(B-rows), 16 warps 4m x 4n, warp 32x64, k-chunk 64
#define NSTAGE  4
#define STAGE_B 49152          // bytes/stage: A 128x64 fp16 = 16KB, B 256x64 fp16 = 32KB
#define B_OFF   16384
#define NTHR    512

// ----------------------------- scratch (static device globals) -------------
__device__ int   g_top2idx[2 * N_TOK];
__device__ float g_top2val[2 * N_TOK];
__device__ int   g_tokens[N_EXP * CAP];
__device__ float g_wts[N_EXP * CAP];
__device__ int   g_slot[2 * N_TOK];
__device__ int   g_counts[N_EXP];
__device__ __align__(256) __half g_Xh [(size_t)N_TOK * H_DIM];             // x fp16 permuted
__device__ __align__(256) __half g_Wgu[(size_t)N_EXP * 2 * I_DIM * H_DIM]; // interleaved g/u rows
__device__ __align__(256) __half g_Wdh[(size_t)N_EXP * H_DIM * I_DIM];     // Wd fp16 permuted
__device__ __align__(256) __half g_Ph [(size_t)N_EXP * CAP * I_DIM];       // swiglu out (fp16, permuted)
__device__ float g_O[(size_t)N_EXP * CAP * H_DIM];                         // per-slot down output

// ----------------------------- helpers -------------------------------------
__device__ __forceinline__ uint32_t smem_u32(const void* p) {
    uint32_t a;
    asm("{ .reg .u64 t; cvta.to.shared.u64 t, %1; cvt.u32.u64 %0, t; }"
        : "=r"(a) : "l"(p));
    return a;
}
// fragment-contiguous permutation within a 32-elem (64B) k-block:
// thread t4 owns fp16 positions [t4*8, t4*8+8) = {c0:k=2t4,2t4+1,2t4+8,2t4+9; c1:+16}
__device__ __forceinline__ int perm32(int j) {
    int kk = j & 15;
    return ((kk >> 1) & 3) * 8 + (j >> 4) * 4 + (kk >> 3) * 2 + (kk & 1);
}
__device__ __forceinline__ void cpa16(uint32_t dst, const void* src) {
    asm volatile("cp.async.cg.shared.global [%0], [%1], 16;" :: "r"(dst), "l"(src));
}
__device__ __forceinline__ void cpa_commit() {
    asm volatile("cp.async.commit_group;" ::: "memory");
}
__device__ __forceinline__ void cpa_wait2() {
    asm volatile("cp.async.wait_group 2;" ::: "memory");
}
__device__ __forceinline__ void mma_f16(float* c, uint32_t a0, uint32_t a1,
                                        uint32_t a2, uint32_t a3,
                                        uint32_t b0, uint32_t b1) {
    asm volatile(
        "mma.sync.aligned.m16n8k16.row.col.f32.f16.f16.f32 "
        "{%0,%1,%2,%3}, {%4,%5,%6,%7}, {%8,%9}, {%0,%1,%2,%3};"
        : "+f"(c[0]), "+f"(c[1]), "+f"(c[2]), "+f"(c[3])
        : "r"(a0), "r"(a1), "r"(a2), "r"(a3), "r"(b0), "r"(b1));
}
// pack 32 fp32 -> 32 fp16 with perm32 layout, write as 4x uint4 (64B)
__device__ __forceinline__ void pack32(const float* v, uint4* dst) {
    unsigned short h[32];
#pragma unroll
    for (int j = 0; j < 32; j++)
        h[perm32(j)] = __half_as_ushort(__float2half_rn(v[j]));
    unsigned w[16];
#pragma unroll
    for (int i = 0; i < 16; i++)
        w[i] = (unsigned)h[2 * i] | ((unsigned)h[2 * i + 1] << 16);
    dst[0] = make_uint4(w[0],  w[1],  w[2],  w[3]);
    dst[1] = make_uint4(w[4],  w[5],  w[6],  w[7]);
    dst[2] = make_uint4(w[8],  w[9],  w[10], w[11]);
    dst[3] = make_uint4(w[12], w[13], w[14], w[15]);
}

// ----------------------------- router --------------------------------------
__global__ void router_kernel(const float* __restrict__ x, const float* __restrict__ Wr) {
    const int warp = threadIdx.x >> 5;
    const int lane = threadIdx.x & 31;
    const int n = blockIdx.x * 8 + warp;

    const float4* xr = reinterpret_cast<const float4*>(x) + (size_t)n * (H_DIM / 4);
    const float4* wr = reinterpret_cast<const float4*>(Wr);

    float acc[N_EXP];
#pragma unroll
    for (int e = 0; e < N_EXP; e++) acc[e] = 0.f;

    for (int i = lane; i < H_DIM / 4; i += 32) {
        float4 xv = xr[i];
#pragma unroll
        for (int e = 0; e < N_EXP; e++) {
            float4 wv = wr[e * (H_DIM / 4) + i];
            acc[e] += xv.x * wv.x + xv.y * wv.y + xv.z * wv.z + xv.w * wv.w;
        }
    }
#pragma unroll
    for (int off = 16; off > 0; off >>= 1) {
#pragma unroll
        for (int e = 0; e < N_EXP; e++)
            acc[e] += __shfl_xor_sync(0xffffffffu, acc[e], off);
    }

    if (lane == 0) {
        float m = acc[0];
#pragma unroll
        for (int e = 1; e < N_EXP; e++) m = fmaxf(m, acc[e]);
        float ex[N_EXP];
        float s = 0.f;
#pragma unroll
        for (int e = 0; e < N_EXP; e++) { ex[e] = __expf(acc[e] - m); s += ex[e]; }
        float inv = 1.f / s;

        float v1 = -1.f; int i1 = 0;
#pragma unroll
        for (int e = 0; e < N_EXP; e++) if (ex[e] > v1) { v1 = ex[e]; i1 = e; }
        float v2 = -1.f; int i2 = 0;
#pragma unroll
        for (int e = 0; e < N_EXP; e++) if (e != i1 && ex[e] > v2) { v2 = ex[e]; i2 = e; }

        g_top2idx[n]         = i1;
        g_top2idx[N_TOK + n] = i2;
        g_top2val[n]         = v1 * inv;
        g_top2val[N_TOK + n] = v2 * inv;
    }
}

// ----------------------------- capacity scheduler ---------------------------
__global__ void sched_kernel() {
    const int tid  = threadIdx.x;           // 0..1023
    const int lane = tid & 31;
    const int wid  = tid >> 5;

    for (int i = tid; i < N_EXP * CAP; i += 1024) {
        g_tokens[i] = 0;
        g_wts[i] = 0.f;
    }

    int   e_loc[8];
    float v_loc[8];
    unsigned pk[4] = {0u, 0u, 0u, 0u};
#pragma unroll
    for (int j = 0; j < 8; j++) {
        int p = tid * 8 + j;
        int e = g_top2idx[p];
        e_loc[j] = e;
        v_loc[j] = g_top2val[p];
        pk[e >> 1] += 1u << ((e & 1) * 16);
    }
    unsigned own[4] = {pk[0], pk[1], pk[2], pk[3]};

#pragma unroll
    for (int off = 1; off < 32; off <<= 1) {
#pragma unroll
        for (int w = 0; w < 4; w++) {
            unsigned u = __shfl_up_sync(0xffffffffu, pk[w], off);
            if (lane >= off) pk[w] += u;
        }
    }

    __shared__ unsigned wsum[32][4];
    if (lane == 31) {
#pragma unroll
        for (int w = 0; w < 4; w++) wsum[wid][w] = pk[w];
    }
    __syncthreads();
    if (wid == 0) {
        unsigned q[4];
#pragma unroll
        for (int w = 0; w < 4; w++) q[w] = wsum[lane][w];
#pragma unroll
        for (int off = 1; off < 32; off <<= 1) {
#pragma unroll
            for (int w = 0; w < 4; w++) {
                unsigned u = __shfl_up_sync(0xffffffffu, q[w], off);
                if (lane >= off) q[w] += u;
            }
        }
#pragma unroll
        for (int w = 0; w < 4; w++) wsum[lane][w] = q[w];
    }
    __syncthreads();

    int off8[8];
#pragma unroll
    for (int w = 0; w < 4; w++) {
        unsigned ex = pk[w] - own[w] + (wid ? wsum[wid - 1][w] : 0u);
        off8[2 * w]     = (int)(ex & 0xFFFFu);
        off8[2 * w + 1] = (int)(ex >> 16);
    }

#pragma unroll
    for (int j = 0; j < 8; j++) {
        int e = e_loc[j];
        int r = off8[e]++;
        int p = tid * 8 + j;
        if (r < CAP) {
            g_tokens[e * CAP + r] = p & (N_TOK - 1);
            g_wts[e * CAP + r]    = v_loc[j];
            g_slot[p] = e * CAP + r;
        } else {
            g_slot[p] = -1;
        }
    }

    if (tid == 0) {
#pragma unroll
        for (int e = 0; e < N_EXP; e++) {
            unsigned u = wsum[31][e >> 1];
            unsigned tot = (e & 1) ? (u >> 16) : (u & 0xFFFFu);
            g_counts[e] = (tot > CAP) ? CAP : (int)tot;
        }
    }
}

// ----------------------------- fp16 prep (vectorized, coalesced) ------------
__global__ void prep_x(const float* __restrict__ x) {
    const int t = blockIdx.x * 256 + threadIdx.x;      // over N_TOK*H/32 blocks
    const float4* src = reinterpret_cast<const float4*>(x) + (size_t)t * 8;
    float v[32];
#pragma unroll
    for (int i = 0; i < 8; i++) {
        float4 f = src[i];
        v[i * 4] = f.x; v[i * 4 + 1] = f.y; v[i * 4 + 2] = f.z; v[i * 4 + 3] = f.w;
    }
    pack32(v, reinterpret_cast<uint4*>(g_Xh) + (size_t)t * 4);
}
// split: blockIdx.y = 0 -> gate rows (2i), 1 -> up rows (2i+1)
__global__ void prep_wgu(const float* __restrict__ Wg, const float* __restrict__ Wu) {
    const int t = blockIdx.x * 256 + threadIdx.x;      // over E*I*(H/32)
    const int kb = t & 63;                              // H/32 = 64
    const int ei = t >> 6;                              // e*I + i
    const int e  = ei / I_DIM;
    const int i  = ei - e * I_DIM;
    const int y  = blockIdx.y;
    const float* W = y ? Wu : Wg;
    const size_t srcb = (size_t)ei * (H_DIM / 4) + kb * 8;
    const size_t dstb = ((size_t)e * 2 * I_DIM + 2 * i + y) * (H_DIM / 8) + kb * 4;
    float v[32];
    const float4* sw = reinterpret_cast<const float4*>(W) + srcb;
#pragma unroll
    for (int q = 0; q < 8; q++) {
        float4 f = sw[q];
        v[q * 4] = f.x; v[q * 4 + 1] = f.y; v[q * 4 + 2] = f.z; v[q * 4 + 3] = f.w;
    }
    pack32(v, reinterpret_cast<uint4*>(g_Wgu) + dstb);
}
__global__ void prep_wd(const float* __restrict__ Wd) {
    const int t = blockIdx.x * 256 + threadIdx.x;      // over E*H*(I/32)
    const int kb  = t % 44;                             // I/32 = 44
    const int row = t / 44;
    const float4* src = reinterpret_cast<const float4*>(Wd) + (size_t)row * (I_DIM / 4) + kb * 8;
    float v[32];
#pragma unroll
    for (int q = 0; q < 8; q++) {
        float4 f = src[q];
        v[q * 4] = f.x; v[q * 4 + 1] = f.y; v[q * 4 + 2] = f.z; v[q * 4 + 3] = f.w;
    }
    pack32(v, reinterpret_cast<uint4*>(g_Wdh) + (size_t)row * (I_DIM / 8) + kb * 4);
}

// ----------------------------- gate+up GEMM + SwiGLU ------------------------
// B tile 256 rows = 128 I-cols, rows 2i/2i+1 = Wg/Wu (prebuilt in g_Wgu).
// 16 warps 4m x 4n, warp tile 32(m) x 64(B-rows). Epilogue staged via smem.
__global__ __launch_bounds__(NTHR, 1)
void gu_kernel(int e_base) {
    const int e  = e_base + blockIdx.z;
    const int m0 = blockIdx.x * 128;
    const int by = blockIdx.y;                   // I block (128 cols)
    const int n0 = by * 128;
    if (m0 >= g_counts[e]) return;

    extern __shared__ char sm[];
    const uint32_t sbase = smem_u32(sm);

    const int tid  = threadIdx.x;
    const int wid  = tid >> 5;
    const int lane = tid & 31;
    const int g    = lane >> 2;
    const int t4   = lane & 3;
    const int wm   = (wid >> 2) * 32;
    const int wn   = (wid & 3) * 64;
    const int gp   = g & 1;                      // row parity of fragment rows

    // loaders: 512 threads; r = tid>>3 (0..63), slice s (16B) of 128B row-chunk
    const int r  = tid >> 3;
    const int s  = tid & 7;
    const int rp = r & 1;                        // parity same for r, r+64, r+128, r+192
    const uint32_t sl = ((s >> 2) ^ rp) * 64 + (s & 3) * 16;  // swizzled 16B slot

    const char* srcA[2]; uint32_t dA[2];
    const char* srcB[4]; uint32_t dB[4];
#pragma unroll
    for (int j = 0; j < 2; j++) {
        int row = r + j * 64;
        srcA[j] = (const char*)(g_Xh + (size_t)g_tokens[e * CAP + m0 + row] * H_DIM) + s * 16;
        dA[j] = (uint32_t)(row * 128) + sl;
    }
#pragma unroll
    for (int j = 0; j < 4; j++) {
        int row = r + j * 64;
        srcB[j] = (const char*)(g_Wgu + ((size_t)e * 2 * I_DIM + (size_t)by * 256 + row) * H_DIM) + s * 16;
        dB[j] = (uint32_t)(B_OFF + row * 128) + sl;
    }

    auto LOAD = [&](int c, int buf) {
        const uint32_t b = sbase + buf * STAGE_B;
        const size_t off = (size_t)c * 128;
#pragma unroll
        for (int j = 0; j < 2; j++) cpa16(b + dA[j], srcA[j] + off);
#pragma unroll
        for (int j = 0; j < 4; j++) cpa16(b + dB[j], srcB[j] + off);
    };

    float acc[2][8][4];
#pragma unroll
    for (int mt = 0; mt < 2; mt++)
#pragma unroll
        for (int nt = 0; nt < 8; nt++)
#pragma unroll
            for (int qq = 0; qq < 4; qq++) acc[mt][nt][qq] = 0.f;

    const int KT = H_DIM / 64;   // 32
    LOAD(0, 0); cpa_commit();
    LOAD(1, 1); cpa_commit();
    LOAD(2, 2); cpa_commit();

#pragma unroll 1
    for (int c = 0; c < KT; c++) {
        cpa_wait2();
        __syncthreads();
        if (c + 3 < KT) LOAD(c + 3, (c + 3) & 3);
        cpa_commit();

        const char* st = sm + (c & 3) * STAGE_B;
#pragma unroll
        for (int ks = 0; ks < 2; ks++) {
            const int col = (ks ^ gp) * 64 + t4 * 16;
            uint4 aLo[2], aHi[2];
#pragma unroll
            for (int mt = 0; mt < 2; mt++) {
                const int row = wm + mt * 16 + g;
                aLo[mt] = *reinterpret_cast<const uint4*>(st + row * 128 + col);
                aHi[mt] = *reinterpret_cast<const uint4*>(st + (row + 8) * 128 + col);
            }
#pragma unroll
            for (int nt = 0; nt < 8; nt++) {
                const int row = wn + nt * 8 + g;
                uint4 bv = *reinterpret_cast<const uint4*>(st + B_OFF + row * 128 + col);
#pragma unroll
                for (int mt = 0; mt < 2; mt++)
                    mma_f16(acc[mt][nt], aLo[mt].x, aHi[mt].x, aLo[mt].y, aHi[mt].y, bv.x, bv.y);
#pragma unroll
                for (int mt = 0; mt < 2; mt++)
                    mma_f16(acc[mt][nt], aLo[mt].z, aHi[mt].z, aLo[mt].w, aHi[mt].w, bv.z, bv.w);
            }
        }
    }

    // ---- epilogue: stage P tile in smem, then coalesced write-out ----
    __syncthreads();
    __half* Ps = reinterpret_cast<__half*>(sm);
    const int PSTR = 136;                        // halves per row (272B stride)
#pragma unroll
    for (int mt = 0; mt < 2; mt++) {
        const int r0 = wm + mt * 16 + g;
#pragma unroll
        for (int nt = 0; nt < 8; nt++) {
            const int ic  = (wn >> 1) + nt * 4 + t4;      // local I col 0..127
            const int pos = (ic & ~31) + perm32(ic & 31); // even for even ic
            float gv0 = acc[mt][nt][0], uv0 = acc[mt][nt][1];
            float v0 = gv0 * uv0 / (1.f + __expf(-gv0));
            float gv1 = acc[mt][nt][2], uv1 = acc[mt][nt][3];
            float v1 = gv1 * uv1 / (1.f + __expf(-gv1));
            uint32_t h0 = (uint32_t)__half_as_ushort(__float2half_rn(v0));
            uint32_t h1 = (uint32_t)__half_as_ushort(__float2half_rn(v1));
            uint32_t p0 = __shfl_xor_sync(0xffffffffu, h0, 1);
            uint32_t p1 = __shfl_xor_sync(0xffffffffu, h1, 1);
            if ((t4 & 1) == 0) {
                *reinterpret_cast<uint32_t*>(&Ps[r0 * PSTR + pos])       = h0 | (p0 << 16);
                *reinterpret_cast<uint32_t*>(&Ps[(r0 + 8) * PSTR + pos]) = h1 | (p1 << 16);
            }
        }
    }
    __syncthreads();
    {
        const int rr = tid >> 2, part = tid & 3;   // 128 rows x 4 segments of 64B
        const uint4* srcp = reinterpret_cast<const uint4*>(Ps + rr * PSTR + part * 32);
        uint4* dstp = reinterpret_cast<uint4*>(
            g_Ph + ((size_t)e * CAP + m0 + rr) * I_DIM + n0 + part * 32);
#pragma unroll
        for (int q = 0; q < 4; q++) dstp[q] = srcp[q];
    }
}

// ----------------------------- down GEMM ------------------------------------
// 128 x 256(H) tile; A = g_Ph (fp16 permuted), B = g_Wdh. 16 warps 4m x 4n.
__global__ __launch_bounds__(NTHR, 1)
void down_kernel(int e_base) {
    const int e  = e_base + blockIdx.z;
    const int m0 = blockIdx.x * 128;
    const int n0 = blockIdx.y * 256;
    if (m0 >= g_counts[e]) return;

    extern __shared__ char sm[];
    const uint32_t sbase = smem_u32(sm);

    const int tid  = threadIdx.x;
    const int wid  = tid >> 5;
    const int lane = tid & 31;
    const int g    = lane >> 2;
    const int t4   = lane & 3;
    const int wm   = (wid >> 2) * 32;
    const int wn   = (wid & 3) * 64;
    const int gp   = g & 1;

    const int r  = tid >> 3;
    const int s  = tid & 7;
    const int rp = r & 1;
    const uint32_t sl = ((s >> 2) ^ rp) * 64 + (s & 3) * 16;

    const char* srcA[2]; uint32_t dA[2];
    const char* srcB[4]; uint32_t dB[4];
#pragma unroll
    for (int j = 0; j < 2; j++) {
        int row = r + j * 64;
        srcA[j] = (const char*)(g_Ph + ((size_t)e * CAP + m0 + row) * I_DIM) + s * 16;
        dA[j] = (uint32_t)(row * 128) + sl;
    }
#pragma unroll
    for (int j = 0; j < 4; j++) {
        int row = r + j * 64;
        srcB[j] = (const char*)(g_Wdh + ((size_t)e * H_DIM + n0 + row) * I_DIM) + s * 16;
        dB[j] = (uint32_t)(B_OFF + row * 128) + sl;
    }

    auto LOAD = [&](int c, int buf) {
        const uint32_t b = sbase + buf * STAGE_B;
        const size_t off = (size_t)c * 128;
#pragma unroll
        for (int j = 0; j < 2; j++) cpa16(b + dA[j], srcA[j] + off);
#pragma unroll
        for (int j = 0; j < 4; j++) cpa16(b + dB[j], srcB[j] + off);
    };

    float acc[2][8][4];
#pragma unroll
    for (int mt = 0; mt < 2; mt++)
#pragma unroll
        for (int nt = 0; nt < 8; nt++)
#pragma unroll
            for (int qq = 0; qq < 4; qq++) acc[mt][nt][qq] = 0.f;

    const int KT = I_DIM / 64;   // 22
    LOAD(0, 0); cpa_commit();
    LOAD(1, 1); cpa_commit();
    LOAD(2, 2); cpa_commit();

#pragma unroll 1
    for (int c = 0; c < KT; c++) {
        cpa_wait2();
        __syncthreads();
        if (c + 3 < KT) LOAD(c + 3, (c + 3) & 3);
        cpa_commit();

        const char* st = sm + (c & 3) * STAGE_B;
#pragma unroll
        for (int ks = 0; ks < 2; ks++) {
            const int col = (ks ^ gp) * 64 + t4 * 16;
            uint4 aLo[2], aHi[2];
#pragma unroll
            for (int mt = 0; mt < 2; mt++) {
                const int row = wm + mt * 16 + g;
                aLo[mt] = *reinterpret_cast<const uint4*>(st + row * 128 + col);
                aHi[mt] = *reinterpret_cast<const uint4*>(st + (row + 8) * 128 + col);
            }
#pragma unroll
            for (int nt = 0; nt < 8; nt++) {
                const int row = wn + nt * 8 + g;
                uint4 bv = *reinterpret_cast<const uint4*>(st + B_OFF + row * 128 + col);
#pragma unroll
                for (int mt = 0; mt < 2; mt++)
                    mma_f16(acc[mt][nt], aLo[mt].x, aHi[mt].x, aLo[mt].y, aHi[mt].y, bv.x, bv.y);
#pragma unroll
                for (int mt = 0; mt < 2; mt++)
                    mma_f16(acc[mt][nt], aLo[mt].z, aHi[mt].z, aLo[mt].w, aHi[mt].w, bv.z, bv.w);
            }
        }
    }

    // epilogue: raw per-slot rows (natural H order, fp32; 32B sectors full)
    float* Ob = g_O + ((size_t)e * CAP + m0) * H_DIM + n0;
#pragma unroll
    for (int mt = 0; mt < 2; mt++) {
        const int r0 = wm + mt * 16 + g;
#pragma unroll
        for (int nt = 0; nt < 8; nt++) {
            const int cc = wn + nt * 8 + t4 * 2;
            *reinterpret_cast<float2*>(Ob + (size_t)r0 * H_DIM + cc) =
                make_float2(acc[mt][nt][0], acc[mt][nt][1]);
            *reinterpret_cast<float2*>(Ob + (size_t)(r0 + 8) * H_DIM + cc) =
                make_float2(acc[mt][nt][2], acc[mt][nt][3]);
        }
    }
}

// ----------------------------- combine --------------------------------------
__global__ void combine_kernel(float* __restrict__ out) {
    const int idx = blockIdx.x * 256 + threadIdx.x;  // over N_TOK * H_DIM/4
    const int n  = idx >> 9;                         // H_DIM/4 = 512
    const int c4 = idx & 511;
    const int s0 = g_slot[n];
    const int s1 = g_slot[N_TOK + n];
    float4 acc = make_float4(0.f, 0.f, 0.f, 0.f);
    const float4* O4 = reinterpret_cast<const float4*>(g_O);
    if (s0 >= 0) {
        float w = g_wts[s0];
        float4 v = O4[(size_t)s0 * 512 + c4];
        acc.x += w * v.x; acc.y += w * v.y; acc.z += w * v.z; acc.w += w * v.w;
    }
    if (s1 >= 0) {
        float w = g_wts[s1];
        float4 v = O4[(size_t)s1 * 512 + c4];
        acc.x += w * v.x; acc.y += w * v.y; acc.z += w * v.z; acc.w += w * v.w;
    }
    reinterpret_cast<float4*>(out)[idx] = acc;
}

// ----------------------------- launch --------------------------------------
#define DYN_SMEM (NSTAGE * STAGE_B)   // 196608 bytes

extern "C" void kernel_launch(void* const* d_in, const int* in_sizes, int n_in,
                              void* d_out, int out_size) {
    const float* x  = (const float*)d_in[0];
    const float* Wr = (const float*)d_in[1];
    const float* Wg = (const float*)d_in[2];
    const float* Wu = (const float*)d_in[3];
    const float* Wd = (const float*)d_in[4];
    float* out = (float*)d_out;
    (void)in_sizes; (void)n_in; (void)out_size;

    // side streams + events for fork-join graph (host resources, created once)
    static cudaStream_t s1 = nullptr, s2 = nullptr;
    static cudaEvent_t evr = nullptr, ev1 = nullptr, ev2 = nullptr,
                       evx = nullptr, evg1 = nullptr, evd1 = nullptr;
    if (s1 == nullptr) {
        cudaStreamCreateWithFlags(&s1, cudaStreamNonBlocking);
        cudaStreamCreateWithFlags(&s2, cudaStreamNonBlocking);
        cudaEventCreateWithFlags(&evr, cudaEventDisableTiming);
        cudaEventCreateWithFlags(&ev1, cudaEventDisableTiming);
        cudaEventCreateWithFlags(&ev2, cudaEventDisableTiming);
        cudaEventCreateWithFlags(&evx, cudaEventDisableTiming);
        cudaEventCreateWithFlags(&evg1, cudaEventDisableTiming);
        cudaEventCreateWithFlags(&evd1, cudaEventDisableTiming);
    }
    cudaFuncSetAttribute(gu_kernel,   cudaFuncAttributeMaxDynamicSharedMemorySize, DYN_SMEM);
    cudaFuncSetAttribute(down_kernel, cudaFuncAttributeMaxDynamicSharedMemorySize, DYN_SMEM);

    // fork
    cudaEventRecord(evr, 0);
    cudaStreamWaitEvent(s1, evr, 0);
    cudaStreamWaitEvent(s2, evr, 0);

    // chain A (main stream): routing
    router_kernel<<<N_TOK / 8, 256>>>(x, Wr);
    sched_kernel<<<1, 1024>>>();

    // chain B (s1): gate/up weights (single kernel, as in round 10)
    dim3 wgrid((N_EXP * I_DIM * (H_DIM / 32)) / 256, 2);
    prep_wgu<<<wgrid, 256, 0, s1>>>(Wg, Wu);
    cudaEventRecord(ev1, s1);

    // chain C (s2): activations first (gu needs them), then down weights
    prep_x  <<<(N_TOK * H_DIM / 32) / 256, 256, 0, s2>>>(x);
    cudaEventRecord(evx, s2);
    prep_wd <<<(N_EXP * H_DIM * (I_DIM / 32)) / 256, 256, 0, s2>>>(Wd);
    cudaEventRecord(ev2, s2);

    // join (wgu, x) -> gu, split into expert halves back-to-back on main.
    // All weights are ready before gu starts (same deps as round 10).
    cudaStreamWaitEvent(0, ev1, 0);
    cudaStreamWaitEvent(0, evx, 0);
    dim3 ggrid(CAP / 128, I_DIM / 128, N_EXP / 2);   // (10, 11, 4)
    gu_kernel<<<ggrid, NTHR, DYN_SMEM>>>(0);
    cudaEventRecord(evg1, 0);
    gu_kernel<<<ggrid, NTHR, DYN_SMEM>>>(N_EXP / 2);

    // down half1 (experts 0-3) on s1, co-scheduled with gu half2
    cudaStreamWaitEvent(s1, evg1, 0);
    cudaStreamWaitEvent(s1, ev2, 0);
    dim3 dgrid(CAP / 128, H_DIM / 256, N_EXP / 2);   // (10, 8, 4)
    down_kernel<<<dgrid, NTHR, DYN_SMEM, s1>>>(0);
    cudaEventRecord(evd1, s1);

    // down half2 (experts 4-7) on main after gu half2 (+ wd ready)
    cudaStreamWaitEvent(0, ev2, 0);
    down_kernel<<<dgrid, NTHR, DYN_SMEM>>>(N_EXP / 2);

    // combine after both down halves
    cudaStreamWaitEvent(0, evd1, 0);
    combine_kernel<<<(N_TOK * (H_DIM / 4)) / 256, 256>>>(out);
}

// round 13
// speedup vs baseline: 1.0909x; 1.0210x over previous
#include <cuda_runtime.h>
#include <cuda_fp16.h>
#include <cstdint>

// Problem constants
#define N_TOK 4096
#define H_DIM 2048
#define I_DIM 1408
#define N_EXP 8
#define CAP   1280   // int(1.25 * (2*N/E))

// Pipeline: CTA 128(m) x 256(B-rows), 16 warps 4m x 4n, warp 32x64, k-chunk 64
#define NSTAGE  4
#define STAGE_B 49152          // bytes/stage: A 128x64 fp16 = 16KB, B 256x64 fp16 = 32KB
#define B_OFF   16384
#define NTHR    512

// ----------------------------- scratch (static device globals) -------------
__device__ int   g_top2idx[2 * N_TOK];
__device__ float g_top2val[2 * N_TOK];
__device__ int   g_tokens[N_EXP * CAP];
__device__ float g_wts[N_EXP * CAP];
__device__ int   g_slot[2 * N_TOK];
__device__ int   g_counts[N_EXP];
__device__ __align__(256) __half g_Xh [(size_t)N_TOK * H_DIM];             // x fp16 permuted
__device__ __align__(256) __half g_Wgu[(size_t)N_EXP * 2 * I_DIM * H_DIM]; // interleaved g/u rows
__device__ __align__(256) __half g_Wdh[(size_t)N_EXP * H_DIM * I_DIM];     // Wd fp16 permuted
__device__ __align__(256) __half g_Ph [(size_t)N_EXP * CAP * I_DIM];       // swiglu out (fp16, permuted)
__device__ float g_O[(size_t)N_EXP * CAP * H_DIM];                         // per-slot down output

// ----------------------------- helpers -------------------------------------
__device__ __forceinline__ uint32_t smem_u32(const void* p) {
    uint32_t a;
    asm("{ .reg .u64 t; cvta.to.shared.u64 t, %1; cvt.u32.u64 %0, t; }"
        : "=r"(a) : "l"(p));
    return a;
}
// fragment-contiguous permutation within a 32-elem (64B) k-block:
// thread t4 owns fp16 positions [t4*8, t4*8+8) = {c0:k=2t4,2t4+1,2t4+8,2t4+9; c1:+16}
__device__ __forceinline__ int perm32(int j) {
    int kk = j & 15;
    return ((kk >> 1) & 3) * 8 + (j >> 4) * 4 + (kk >> 3) * 2 + (kk & 1);
}
__device__ __forceinline__ void cpa16(uint32_t dst, const void* src) {
    asm volatile("cp.async.cg.shared.global [%0], [%1], 16;" :: "r"(dst), "l"(src));
}
__device__ __forceinline__ void cpa_commit() {
    asm volatile("cp.async.commit_group;" ::: "memory");
}
__device__ __forceinline__ void cpa_wait2() {
    asm volatile("cp.async.wait_group 2;" ::: "memory");
}
__device__ __forceinline__ void mma_f16(float* c, uint32_t a0, uint32_t a1,
                                        uint32_t a2, uint32_t a3,
                                        uint32_t b0, uint32_t b1) {
    asm volatile(
        "mma.sync.aligned.m16n8k16.row.col.f32.f16.f16.f32 "
        "{%0,%1,%2,%3}, {%4,%5,%6,%7}, {%8,%9}, {%0,%1,%2,%3};"
        : "+f"(c[0]), "+f"(c[1]), "+f"(c[2]), "+f"(c[3])
        : "r"(a0), "r"(a1), "r"(a2), "r"(a3), "r"(b0), "r"(b1));
}
// pack 32 fp32 -> 32 fp16 with perm32 layout, write as 4x uint4 (64B)
__device__ __forceinline__ void pack32(const float* v, uint4* dst) {
    unsigned short h[32];
#pragma unroll
    for (int j = 0; j < 32; j++)
        h[perm32(j)] = __half_as_ushort(__float2half_rn(v[j]));
    unsigned w[16];
#pragma unroll
    for (int i = 0; i < 16; i++)
        w[i] = (unsigned)h[2 * i] | ((unsigned)h[2 * i + 1] << 16);
    dst[0] = make_uint4(w[0],  w[1],  w[2],  w[3]);
    dst[1] = make_uint4(w[4],  w[5],  w[6],  w[7]);
    dst[2] = make_uint4(w[8],  w[9],  w[10], w[11]);
    dst[3] = make_uint4(w[12], w[13], w[14], w[15]);
}

// ----------------------------- router --------------------------------------
__global__ void router_kernel(const float* __restrict__ x, const float* __restrict__ Wr) {
    const int warp = threadIdx.x >> 5;
    const int lane = threadIdx.x & 31;
    const int n = blockIdx.x * 8 + warp;

    const float4* xr = reinterpret_cast<const float4*>(x) + (size_t)n * (H_DIM / 4);
    const float4* wr = reinterpret_cast<const float4*>(Wr);

    float acc[N_EXP];
#pragma unroll
    for (int e = 0; e < N_EXP; e++) acc[e] = 0.f;

    for (int i = lane; i < H_DIM / 4; i += 32) {
        float4 xv = xr[i];
#pragma unroll
        for (int e = 0; e < N_EXP; e++) {
            float4 wv = wr[e * (H_DIM / 4) + i];
            acc[e] += xv.x * wv.x + xv.y * wv.y + xv.z * wv.z + xv.w * wv.w;
        }
    }
#pragma unroll
    for (int off = 16; off > 0; off >>= 1) {
#pragma unroll
        for (int e = 0; e < N_EXP; e++)
            acc[e] += __shfl_xor_sync(0xffffffffu, acc[e], off);
    }

    if (lane == 0) {
        float m = acc[0];
#pragma unroll
        for (int e = 1; e < N_EXP; e++) m = fmaxf(m, acc[e]);
        float ex[N_EXP];
        float s = 0.f;
#pragma unroll
        for (int e = 0; e < N_EXP; e++) { ex[e] = __expf(acc[e] - m); s += ex[e]; }
        float inv = 1.f / s;

        float v1 = -1.f; int i1 = 0;
#pragma unroll
        for (int e = 0; e < N_EXP; e++) if (ex[e] > v1) { v1 = ex[e]; i1 = e; }
        float v2 = -1.f; int i2 = 0;
#pragma unroll
        for (int e = 0; e < N_EXP; e++) if (e != i1 && ex[e] > v2) { v2 = ex[e]; i2 = e; }

        g_top2idx[n]         = i1;
        g_top2idx[N_TOK + n] = i2;
        g_top2val[n]         = v1 * inv;
        g_top2val[N_TOK + n] = v2 * inv;
    }
}

// ----------------------------- capacity scheduler ---------------------------
__global__ void sched_kernel() {
    const int tid  = threadIdx.x;           // 0..1023
    const int lane = tid & 31;
    const int wid  = tid >> 5;

    for (int i = tid; i < N_EXP * CAP; i += 1024) {
        g_tokens[i] = 0;
        g_wts[i] = 0.f;
    }

    int   e_loc[8];
    float v_loc[8];
    unsigned pk[4] = {0u, 0u, 0u, 0u};
#pragma unroll
    for (int j = 0; j < 8; j++) {
        int p = tid * 8 + j;
        int e = g_top2idx[p];
        e_loc[j] = e;
        v_loc[j] = g_top2val[p];
        pk[e >> 1] += 1u << ((e & 1) * 16);
    }
    unsigned own[4] = {pk[0], pk[1], pk[2], pk[3]};

#pragma unroll
    for (int off = 1; off < 32; off <<= 1) {
#pragma unroll
        for (int w = 0; w < 4; w++) {
            unsigned u = __shfl_up_sync(0xffffffffu, pk[w], off);
            if (lane >= off) pk[w] += u;
        }
    }

    __shared__ unsigned wsum[32][4];
    if (lane == 31) {
#pragma unroll
        for (int w = 0; w < 4; w++) wsum[wid][w] = pk[w];
    }
    __syncthreads();
    if (wid == 0) {
        unsigned q[4];
#pragma unroll
        for (int w = 0; w < 4; w++) q[w] = wsum[lane][w];
#pragma unroll
        for (int off = 1; off < 32; off <<= 1) {
#pragma unroll
            for (int w = 0; w < 4; w++) {
                unsigned u = __shfl_up_sync(0xffffffffu, q[w], off);
                if (lane >= off) q[w] += u;
            }
        }
#pragma unroll
        for (int w = 0; w < 4; w++) wsum[lane][w] = q[w];
    }
    __syncthreads();

    int off8[8];
#pragma unroll
    for (int w = 0; w < 4; w++) {
        unsigned ex = pk[w] - own[w] + (wid ? wsum[wid - 1][w] : 0u);
        off8[2 * w]     = (int)(ex & 0xFFFFu);
        off8[2 * w + 1] = (int)(ex >> 16);
    }

#pragma unroll
    for (int j = 0; j < 8; j++) {
        int e = e_loc[j];
        int r = off8[e]++;
        int p = tid * 8 + j;
        if (r < CAP) {
            g_tokens[e * CAP + r] = p & (N_TOK - 1);
            g_wts[e * CAP + r]    = v_loc[j];
            g_slot[p] = e * CAP + r;
        } else {
            g_slot[p] = -1;
        }
    }

    if (tid == 0) {
#pragma unroll
        for (int e = 0; e < N_EXP; e++) {
            unsigned u = wsum[31][e >> 1];
            unsigned tot = (e & 1) ? (u >> 16) : (u & 0xFFFFu);
            g_counts[e] = (tot > CAP) ? CAP : (int)tot;
        }
    }
}

// ----------------------------- fp16 prep (vectorized, coalesced) ------------
__global__ void prep_x(const float* __restrict__ x) {
    const int t = blockIdx.x * 256 + threadIdx.x;      // over N_TOK*H/32 blocks
    const float4* src = reinterpret_cast<const float4*>(x) + (size_t)t * 8;
    float v[32];
#pragma unroll
    for (int i = 0; i < 8; i++) {
        float4 f = src[i];
        v[i * 4] = f.x; v[i * 4 + 1] = f.y; v[i * 4 + 2] = f.z; v[i * 4 + 3] = f.w;
    }
    pack32(v, reinterpret_cast<uint4*>(g_Xh) + (size_t)t * 4);
}
// split: blockIdx.y = 0 -> gate rows (2i), 1 -> up rows (2i+1)
__global__ void prep_wgu(const float* __restrict__ Wg, const float* __restrict__ Wu) {
    const int t = blockIdx.x * 256 + threadIdx.x;      // over E*I*(H/32)
    const int kb = t & 63;                              // H/32 = 64
    const int ei = t >> 6;                              // e*I + i
    const int e  = ei / I_DIM;
    const int i  = ei - e * I_DIM;
    const int y  = blockIdx.y;
    const float* W = y ? Wu : Wg;
    const size_t srcb = (size_t)ei * (H_DIM / 4) + kb * 8;
    const size_t dstb = ((size_t)e * 2 * I_DIM + 2 * i + y) * (H_DIM / 8) + kb * 4;
    float v[32];
    const float4* sw = reinterpret_cast<const float4*>(W) + srcb;
#pragma unroll
    for (int q = 0; q < 8; q++) {
        float4 f = sw[q];
        v[q * 4] = f.x; v[q * 4 + 1] = f.y; v[q * 4 + 2] = f.z; v[q * 4 + 3] = f.w;
    }
    pack32(v, reinterpret_cast<uint4*>(g_Wgu) + dstb);
}
__global__ void prep_wd(const float* __restrict__ Wd) {
    const int t = blockIdx.x * 256 + threadIdx.x;      // over E*H*(I/32)
    const int kb  = t % 44;                             // I/32 = 44
    const int row = t / 44;
    const float4* src = reinterpret_cast<const float4*>(Wd) + (size_t)row * (I_DIM / 4) + kb * 8;
    float v[32];
#pragma unroll
    for (int q = 0; q < 8; q++) {
        float4 f = src[q];
        v[q * 4] = f.x; v[q * 4 + 1] = f.y; v[q * 4 + 2] = f.z; v[q * 4 + 3] = f.w;
    }
    pack32(v, reinterpret_cast<uint4*>(g_Wdh) + (size_t)row * (I_DIM / 8) + kb * 4);
}

// ----------------------------- gate+up GEMM + SwiGLU ------------------------
// B tile 256 rows = 128 I-cols, rows 2i/2i+1 = Wg/Wu (prebuilt in g_Wgu).
// 16 warps 4m x 4n, warp tile 32(m) x 64(B-rows). Epilogue staged via smem.
__global__ __launch_bounds__(NTHR, 1)
void gu_kernel() {
    const int e  = blockIdx.z;
    const int m0 = blockIdx.x * 128;
    const int by = blockIdx.y;                   // I block (128 cols)
    const int n0 = by * 128;
    if (m0 >= g_counts[e]) return;

    extern __shared__ char sm[];
    const uint32_t sbase = smem_u32(sm);

    const int tid  = threadIdx.x;
    const int wid  = tid >> 5;
    const int lane = tid & 31;
    const int g    = lane >> 2;
    const int t4   = lane & 3;
    const int wm   = (wid >> 2) * 32;
    const int wn   = (wid & 3) * 64;
    const int gp   = g & 1;                      // row parity of fragment rows

    // loaders: 512 threads; r = tid>>3 (0..63), slice s (16B) of 128B row-chunk
    const int r  = tid >> 3;
    const int s  = tid & 7;
    const int rp = r & 1;                        // parity same for r, r+64, r+128, r+192
    const uint32_t sl = ((s >> 2) ^ rp) * 64 + (s & 3) * 16;  // swizzled 16B slot

    const char* srcA[2]; uint32_t dA[2];
    const char* srcB[4]; uint32_t dB[4];
#pragma unroll
    for (int j = 0; j < 2; j++) {
        int row = r + j * 64;
        srcA[j] = (const char*)(g_Xh + (size_t)g_tokens[e * CAP + m0 + row] * H_DIM) + s * 16;
        dA[j] = (uint32_t)(row * 128) + sl;
    }
#pragma unroll
    for (int j = 0; j < 4; j++) {
        int row = r + j * 64;
        srcB[j] = (const char*)(g_Wgu + ((size_t)e * 2 * I_DIM + (size_t)by * 256 + row) * H_DIM) + s * 16;
        dB[j] = (uint32_t)(B_OFF + row * 128) + sl;
    }

    auto LOAD = [&](int c, int buf) {
        const uint32_t b = sbase + buf * STAGE_B;
        const size_t off = (size_t)c * 128;
#pragma unroll
        for (int j = 0; j < 2; j++) cpa16(b + dA[j], srcA[j] + off);
#pragma unroll
        for (int j = 0; j < 4; j++) cpa16(b + dB[j], srcB[j] + off);
    };

    float acc[2][8][4];
#pragma unroll
    for (int mt = 0; mt < 2; mt++)
#pragma unroll
        for (int nt = 0; nt < 8; nt++)
#pragma unroll
            for (int qq = 0; qq < 4; qq++) acc[mt][nt][qq] = 0.f;

    const int KT = H_DIM / 64;   // 32
    LOAD(0, 0); cpa_commit();
    LOAD(1, 1); cpa_commit();
    LOAD(2, 2); cpa_commit();

#pragma unroll 1
    for (int c = 0; c < KT; c++) {
        cpa_wait2();
        __syncthreads();
        if (c + 3 < KT) LOAD(c + 3, (c + 3) & 3);
        cpa_commit();

        const char* st = sm + (c & 3) * STAGE_B;
#pragma unroll
        for (int ks = 0; ks < 2; ks++) {
            const int col = (ks ^ gp) * 64 + t4 * 16;
            uint4 aLo[2], aHi[2];
#pragma unroll
            for (int mt = 0; mt < 2; mt++) {
                const int row = wm + mt * 16 + g;
                aLo[mt] = *reinterpret_cast<const uint4*>(st + row * 128 + col);
                aHi[mt] = *reinterpret_cast<const uint4*>(st + (row + 8) * 128 + col);
            }
#pragma unroll
            for (int nt = 0; nt < 8; nt++) {
                const int row = wn + nt * 8 + g;
                uint4 bv = *reinterpret_cast<const uint4*>(st + B_OFF + row * 128 + col);
#pragma unroll
                for (int mt = 0; mt < 2; mt++)
                    mma_f16(acc[mt][nt], aLo[mt].x, aHi[mt].x, aLo[mt].y, aHi[mt].y, bv.x, bv.y);
#pragma unroll
                for (int mt = 0; mt < 2; mt++)
                    mma_f16(acc[mt][nt], aLo[mt].z, aHi[mt].z, aLo[mt].w, aHi[mt].w, bv.z, bv.w);
            }
        }
    }

    // ---- epilogue: stage P tile in smem, then coalesced write-out ----
    __syncthreads();
    __half* Ps = reinterpret_cast<__half*>(sm);
    const int PSTR = 136;                        // halves per row (272B stride)
#pragma unroll
    for (int mt = 0; mt < 2; mt++) {
        const int r0 = wm + mt * 16 + g;
#pragma unroll
        for (int nt = 0; nt < 8; nt++) {
            const int ic  = (wn >> 1) + nt * 4 + t4;      // local I col 0..127
            const int pos = (ic & ~31) + perm32(ic & 31); // even for even ic
            float gv0 = acc[mt][nt][0], uv0 = acc[mt][nt][1];
            float v0 = gv0 * uv0 / (1.f + __expf(-gv0));
            float gv1 = acc[mt][nt][2], uv1 = acc[mt][nt][3];
            float v1 = gv1 * uv1 / (1.f + __expf(-gv1));
            uint32_t h0 = (uint32_t)__half_as_ushort(__float2half_rn(v0));
            uint32_t h1 = (uint32_t)__half_as_ushort(__float2half_rn(v1));
            uint32_t p0 = __shfl_xor_sync(0xffffffffu, h0, 1);
            uint32_t p1 = __shfl_xor_sync(0xffffffffu, h1, 1);
            if ((t4 & 1) == 0) {
                *reinterpret_cast<uint32_t*>(&Ps[r0 * PSTR + pos])       = h0 | (p0 << 16);
                *reinterpret_cast<uint32_t*>(&Ps[(r0 + 8) * PSTR + pos]) = h1 | (p1 << 16);
            }
        }
    }
    __syncthreads();
    {
        const int rr = tid >> 2, part = tid & 3;   // 128 rows x 4 segments of 64B
        const uint4* srcp = reinterpret_cast<const uint4*>(Ps + rr * PSTR + part * 32);
        uint4* dstp = reinterpret_cast<uint4*>(
            g_Ph + ((size_t)e * CAP + m0 + rr) * I_DIM + n0 + part * 32);
#pragma unroll
        for (int q = 0; q < 4; q++) dstp[q] = srcp[q];
    }
}

// ----------------------------- down GEMM ------------------------------------
// 128 x 256(H) tile; A = g_Ph (fp16 permuted), B = g_Wdh. 16 warps 4m x 4n.
__global__ __launch_bounds__(NTHR, 1)
void down_kernel() {
    const int e  = blockIdx.z;
    const int m0 = blockIdx.x * 128;
    const int n0 = blockIdx.y * 256;
    if (m0 >= g_counts[e]) return;

    extern __shared__ char sm[];
    const uint32_t sbase = smem_u32(sm);

    const int tid  = threadIdx.x;
    const int wid  = tid >> 5;
    const int lane = tid & 31;
    const int g    = lane >> 2;
    const int t4   = lane & 3;
    const int wm   = (wid >> 2) * 32;
    const int wn   = (wid & 3) * 64;
    const int gp   = g & 1;

    const int r  = tid >> 3;
    const int s  = tid & 7;
    const int rp = r & 1;
    const uint32_t sl = ((s >> 2) ^ rp) * 64 + (s & 3) * 16;

    const char* srcA[2]; uint32_t dA[2];
    const char* srcB[4]; uint32_t dB[4];
#pragma unroll
    for (int j = 0; j < 2; j++) {
        int row = r + j * 64;
        srcA[j] = (const char*)(g_Ph + ((size_t)e * CAP + m0 + row) * I_DIM) + s * 16;
        dA[j] = (uint32_t)(row * 128) + sl;
    }
#pragma unroll
    for (int j = 0; j < 4; j++) {
        int row = r + j * 64;
        srcB[j] = (const char*)(g_Wdh + ((size_t)e * H_DIM + n0 + row) * I_DIM) + s * 16;
        dB[j] = (uint32_t)(B_OFF + row * 128) + sl;
    }

    auto LOAD = [&](int c, int buf) {
        const uint32_t b = sbase + buf * STAGE_B;
        const size_t off = (size_t)c * 128;
#pragma unroll
        for (int j = 0; j < 2; j++) cpa16(b + dA[j], srcA[j] + off);
#pragma unroll
        for (int j = 0; j < 4; j++) cpa16(b + dB[j], srcB[j] + off);
    };

    float acc[2][8][4];
#pragma unroll
    for (int mt = 0; mt < 2; mt++)
#pragma unroll
        for (int nt = 0; nt < 8; nt++)
#pragma unroll
            for (int qq = 0; qq < 4; qq++) acc[mt][nt][qq] = 0.f;

    const int KT = I_DIM / 64;   // 22
    LOAD(0, 0); cpa_commit();
    LOAD(1, 1); cpa_commit();
    LOAD(2, 2); cpa_commit();

#pragma unroll 1
    for (int c = 0; c < KT; c++) {
        cpa_wait2();
        __syncthreads();
        if (c + 3 < KT) LOAD(c + 3, (c + 3) & 3);
        cpa_commit();

        const char* st = sm + (c & 3) * STAGE_B;
#pragma unroll
        for (int ks = 0; ks < 2; ks++) {
            const int col = (ks ^ gp) * 64 + t4 * 16;
            uint4 aLo[2], aHi[2];
#pragma unroll
            for (int mt = 0; mt < 2; mt++) {
                const int row = wm + mt * 16 + g;
                aLo[mt] = *reinterpret_cast<const uint4*>(st + row * 128 + col);
                aHi[mt] = *reinterpret_cast<const uint4*>(st + (row + 8) * 128 + col);
            }
#pragma unroll
            for (int nt = 0; nt < 8; nt++) {
                const int row = wn + nt * 8 + g;
                uint4 bv = *reinterpret_cast<const uint4*>(st + B_OFF + row * 128 + col);
#pragma unroll
                for (int mt = 0; mt < 2; mt++)
                    mma_f16(acc[mt][nt], aLo[mt].x, aHi[mt].x, aLo[mt].y, aHi[mt].y, bv.x, bv.y);
#pragma unroll
                for (int mt = 0; mt < 2; mt++)
                    mma_f16(acc[mt][nt], aLo[mt].z, aHi[mt].z, aLo[mt].w, aHi[mt].w, bv.z, bv.w);
            }
        }
    }

    // epilogue: raw per-slot rows (natural H order, fp32; 32B sectors full)
    float* Ob = g_O + ((size_t)e * CAP + m0) * H_DIM + n0;
#pragma unroll
    for (int mt = 0; mt < 2; mt++) {
        const int r0 = wm + mt * 16 + g;
#pragma unroll
        for (int nt = 0; nt < 8; nt++) {
            const int cc = wn + nt * 8 + t4 * 2;
            *reinterpret_cast<float2*>(Ob + (size_t)r0 * H_DIM + cc) =
                make_float2(acc[mt][nt][0], acc[mt][nt][1]);
            *reinterpret_cast<float2*>(Ob + (size_t)(r0 + 8) * H_DIM + cc) =
                make_float2(acc[mt][nt][2], acc[mt][nt][3]);
        }
    }
}

// ----------------------------- combine --------------------------------------
__global__ void combine_kernel(float* __restrict__ out) {
    const int idx = blockIdx.x * 512 + threadIdx.x;  // over N_TOK * H_DIM/4
    const int n  = idx >> 9;                         // H_DIM/4 = 512
    const int c4 = idx & 511;
    const int s0 = g_slot[n];
    const int s1 = g_slot[N_TOK + n];
    float4 acc = make_float4(0.f, 0.f, 0.f, 0.f);
    const float4* O4 = reinterpret_cast<const float4*>(g_O);
    if (s0 >= 0) {
        float w = g_wts[s0];
        float4 v = O4[(size_t)s0 * 512 + c4];
        acc.x += w * v.x; acc.y += w * v.y; acc.z += w * v.z; acc.w += w * v.w;
    }
    if (s1 >= 0) {
        float w = g_wts[s1];
        float4 v = O4[(size_t)s1 * 512 + c4];
        acc.x += w * v.x; acc.y += w * v.y; acc.z += w * v.z; acc.w += w * v.w;
    }
    reinterpret_cast<float4*>(out)[idx] = acc;
}

// ----------------------------- launch --------------------------------------
#define DYN_SMEM (NSTAGE * STAGE_B)   // 196608 bytes

extern "C" void kernel_launch(void* const* d_in, const int* in_sizes, int n_in,
                              void* d_out, int out_size) {
    const float* x  = (const float*)d_in[0];
    const float* Wr = (const float*)d_in[1];
    const float* Wg = (const float*)d_in[2];
    const float* Wu = (const float*)d_in[3];
    const float* Wd = (const float*)d_in[4];
    float* out = (float*)d_out;
    (void)in_sizes; (void)n_in; (void)out_size;

    // side streams + events for fork-join graph (host resources, created once)
    static cudaStream_t s1 = nullptr, s2 = nullptr;
    static cudaEvent_t evr = nullptr, ev1 = nullptr, ev2 = nullptr, evx = nullptr;
    if (s1 == nullptr) {
        cudaStreamCreateWithFlags(&s1, cudaStreamNonBlocking);
        cudaStreamCreateWithFlags(&s2, cudaStreamNonBlocking);
        cudaEventCreateWithFlags(&evr, cudaEventDisableTiming);
        cudaEventCreateWithFlags(&ev1, cudaEventDisableTiming);
        cudaEventCreateWithFlags(&ev2, cudaEventDisableTiming);
        cudaEventCreateWithFlags(&evx, cudaEventDisableTiming);
    }
    cudaFuncSetAttribute(gu_kernel,   cudaFuncAttributeMaxDynamicSharedMemorySize, DYN_SMEM);
    cudaFuncSetAttribute(down_kernel, cudaFuncAttributeMaxDynamicSharedMemorySize, DYN_SMEM);

    // fork
    cudaEventRecord(evr, 0);
    cudaStreamWaitEvent(s1, evr, 0);
    cudaStreamWaitEvent(s2, evr, 0);

    // chain A (main stream): routing
    router_kernel<<<N_TOK / 8, 256>>>(x, Wr);
    sched_kernel<<<1, 1024>>>();

    // chain B (s1): gate/up weights only (critical path to gu)
    dim3 wgrid((N_EXP * I_DIM * (H_DIM / 32)) / 256, 2);
    prep_wgu<<<wgrid, 256, 0, s1>>>(Wg, Wu);
    cudaEventRecord(ev1, s1);

    // chain C (s2): activations first (gu needs them), then down weights
    prep_x  <<<(N_TOK * H_DIM / 32) / 256, 256, 0, s2>>>(x);
    cudaEventRecord(evx, s2);
    prep_wd <<<(N_EXP * H_DIM * (I_DIM / 32)) / 256, 256, 0, s2>>>(Wd);
    cudaEventRecord(ev2, s2);

    // join (wgu, x) -> gu
    cudaStreamWaitEvent(0, ev1, 0);
    cudaStreamWaitEvent(0, evx, 0);
    dim3 ggrid(CAP / 128, I_DIM / 128, N_EXP);   // (10, 11, 8), m fastest for L2 reuse
    gu_kernel<<<ggrid, NTHR, DYN_SMEM>>>();

    // join wd -> down (prep_wd hides under gu)
    cudaStreamWaitEvent(0, ev2, 0);
    dim3 dgrid(CAP / 128, H_DIM / 256, N_EXP);   // (10, 8, 8)
    down_kernel<<<dgrid, NTHR, DYN_SMEM>>>();

    combine_kernel<<<(N_TOK * (H_DIM / 4)) / 512, 512>>>(out);
}

// round 14
// speedup vs baseline: 1.1081x; 1.0157x over previous
#include <cuda_runtime.h>
#include <cuda_fp16.h>
#include <cstdint>

// Problem constants
#define N_TOK 4096
#define H_DIM 2048
#define I_DIM 1408
#define N_EXP 8
#define CAP   1280   // int(1.25 * (2*N/E))

// Pipeline: CTA 128(m) x 256(B-rows), 16 warps 4m x 4n, warp 32x64, k-chunk 64
#define NSTAGE  4
#define STAGE_B 49152          // bytes/stage: A 128x64 fp16 = 16KB, B 256x64 fp16 = 32KB
#define B_OFF   16384
#define NTHR    512

// ----------------------------- scratch (static device globals) -------------
__device__ int   g_top2idx[2 * N_TOK];
__device__ float g_top2val[2 * N_TOK];
__device__ int   g_tokens[N_EXP * CAP];
__device__ float g_wts[N_EXP * CAP];
__device__ int   g_slot[2 * N_TOK];
__device__ int   g_counts[N_EXP];
__device__ __align__(256) __half g_Xh [(size_t)N_TOK * H_DIM];             // x fp16 permuted
__device__ __align__(256) __half g_Wgu[(size_t)N_EXP * 2 * I_DIM * H_DIM]; // interleaved g/u rows
__device__ __align__(256) __half g_Wdh[(size_t)N_EXP * H_DIM * I_DIM];     // Wd fp16 permuted
__device__ __align__(256) __half g_Ph [(size_t)N_EXP * CAP * I_DIM];       // swiglu out (fp16, permuted)
__device__ __align__(256) __half g_O  [(size_t)N_EXP * CAP * H_DIM];       // per-slot down output (fp16)

// ----------------------------- helpers -------------------------------------
__device__ __forceinline__ uint32_t smem_u32(const void* p) {
    uint32_t a;
    asm("{ .reg .u64 t; cvta.to.shared.u64 t, %1; cvt.u32.u64 %0, t; }"
        : "=r"(a) : "l"(p));
    return a;
}
// fragment-contiguous permutation within a 32-elem (64B) k-block:
// thread t4 owns fp16 positions [t4*8, t4*8+8) = {c0:k=2t4,2t4+1,2t4+8,2t4+9; c1:+16}
__device__ __forceinline__ int perm32(int j) {
    int kk = j & 15;
    return ((kk >> 1) & 3) * 8 + (j >> 4) * 4 + (kk >> 3) * 2 + (kk & 1);
}
__device__ __forceinline__ void cpa16(uint32_t dst, const void* src) {
    asm volatile("cp.async.cg.shared.global [%0], [%1], 16;" :: "r"(dst), "l"(src));
}
__device__ __forceinline__ void cpa_commit() {
    asm volatile("cp.async.commit_group;" ::: "memory");
}
__device__ __forceinline__ void cpa_wait2() {
    asm volatile("cp.async.wait_group 2;" ::: "memory");
}
__device__ __forceinline__ void mma_f16(float* c, uint32_t a0, uint32_t a1,
                                        uint32_t a2, uint32_t a3,
                                        uint32_t b0, uint32_t b1) {
    asm volatile(
        "mma.sync.aligned.m16n8k16.row.col.f32.f16.f16.f32 "
        "{%0,%1,%2,%3}, {%4,%5,%6,%7}, {%8,%9}, {%0,%1,%2,%3};"
        : "+f"(c[0]), "+f"(c[1]), "+f"(c[2]), "+f"(c[3])
        : "r"(a0), "r"(a1), "r"(a2), "r"(a3), "r"(b0), "r"(b1));
}
// pack 32 fp32 -> 32 fp16 with perm32 layout, write as 4x uint4 (64B)
__device__ __forceinline__ void pack32(const float* v, uint4* dst) {
    unsigned short h[32];
#pragma unroll
    for (int j = 0; j < 32; j++)
        h[perm32(j)] = __half_as_ushort(__float2half_rn(v[j]));
    unsigned w[16];
#pragma unroll
    for (int i = 0; i < 16; i++)
        w[i] = (unsigned)h[2 * i] | ((unsigned)h[2 * i + 1] << 16);
    dst[0] = make_uint4(w[0],  w[1],  w[2],  w[3]);
    dst[1] = make_uint4(w[4],  w[5],  w[6],  w[7]);
    dst[2] = make_uint4(w[8],  w[9],  w[10], w[11]);
    dst[3] = make_uint4(w[12], w[13], w[14], w[15]);
}

// ----------------------------- router --------------------------------------
__global__ void router_kernel(const float* __restrict__ x, const float* __restrict__ Wr) {
    const int warp = threadIdx.x >> 5;
    const int lane = threadIdx.x & 31;
    const int n = blockIdx.x * 8 + warp;

    const float4* xr = reinterpret_cast<const float4*>(x) + (size_t)n * (H_DIM / 4);
    const float4* wr = reinterpret_cast<const float4*>(Wr);

    float acc[N_EXP];
#pragma unroll
    for (int e = 0; e < N_EXP; e++) acc[e] = 0.f;

    for (int i = lane; i < H_DIM / 4; i += 32) {
        float4 xv = xr[i];
#pragma unroll
        for (int e = 0; e < N_EXP; e++) {
            float4 wv = wr[e * (H_DIM / 4) + i];
            acc[e] += xv.x * wv.x + xv.y * wv.y + xv.z * wv.z + xv.w * wv.w;
        }
    }
#pragma unroll
    for (int off = 16; off > 0; off >>= 1) {
#pragma unroll
        for (int e = 0; e < N_EXP; e++)
            acc[e] += __shfl_xor_sync(0xffffffffu, acc[e], off);
    }

    if (lane == 0) {
        float m = acc[0];
#pragma unroll
        for (int e = 1; e < N_EXP; e++) m = fmaxf(m, acc[e]);
        float ex[N_EXP];
        float s = 0.f;
#pragma unroll
        for (int e = 0; e < N_EXP; e++) { ex[e] = __expf(acc[e] - m); s += ex[e]; }
        float inv = 1.f / s;

        float v1 = -1.f; int i1 = 0;
#pragma unroll
        for (int e = 0; e < N_EXP; e++) if (ex[e] > v1) { v1 = ex[e]; i1 = e; }
        float v2 = -1.f; int i2 = 0;
#pragma unroll
        for (int e = 0; e < N_EXP; e++) if (e != i1 && ex[e] > v2) { v2 = ex[e]; i2 = e; }

        g_top2idx[n]         = i1;
        g_top2idx[N_TOK + n] = i2;
        g_top2val[n]         = v1 * inv;
        g_top2val[N_TOK + n] = v2 * inv;
    }
}

// ----------------------------- capacity scheduler ---------------------------
__global__ void sched_kernel() {
    const int tid  = threadIdx.x;           // 0..1023
    const int lane = tid & 31;
    const int wid  = tid >> 5;

    for (int i = tid; i < N_EXP * CAP; i += 1024) {
        g_tokens[i] = 0;
        g_wts[i] = 0.f;
    }

    int   e_loc[8];
    float v_loc[8];
    unsigned pk[4] = {0u, 0u, 0u, 0u};
#pragma unroll
    for (int j = 0; j < 8; j++) {
        int p = tid * 8 + j;
        int e = g_top2idx[p];
        e_loc[j] = e;
        v_loc[j] = g_top2val[p];
        pk[e >> 1] += 1u << ((e & 1) * 16);
    }
    unsigned own[4] = {pk[0], pk[1], pk[2], pk[3]};

#pragma unroll
    for (int off = 1; off < 32; off <<= 1) {
#pragma unroll
        for (int w = 0; w < 4; w++) {
            unsigned u = __shfl_up_sync(0xffffffffu, pk[w], off);
            if (lane >= off) pk[w] += u;
        }
    }

    __shared__ unsigned wsum[32][4];
    if (lane == 31) {
#pragma unroll
        for (int w = 0; w < 4; w++) wsum[wid][w] = pk[w];
    }
    __syncthreads();
    if (wid == 0) {
        unsigned q[4];
#pragma unroll
        for (int w = 0; w < 4; w++) q[w] = wsum[lane][w];
#pragma unroll
        for (int off = 1; off < 32; off <<= 1) {
#pragma unroll
            for (int w = 0; w < 4; w++) {
                unsigned u = __shfl_up_sync(0xffffffffu, q[w], off);
                if (lane >= off) q[w] += u;
            }
        }
#pragma unroll
        for (int w = 0; w < 4; w++) wsum[lane][w] = q[w];
    }
    __syncthreads();

    int off8[8];
#pragma unroll
    for (int w = 0; w < 4; w++) {
        unsigned ex = pk[w] - own[w] + (wid ? wsum[wid - 1][w] : 0u);
        off8[2 * w]     = (int)(ex & 0xFFFFu);
        off8[2 * w + 1] = (int)(ex >> 16);
    }

#pragma unroll
    for (int j = 0; j < 8; j++) {
        int e = e_loc[j];
        int r = off8[e]++;
        int p = tid * 8 + j;
        if (r < CAP) {
            g_tokens[e * CAP + r] = p & (N_TOK - 1);
            g_wts[e * CAP + r]    = v_loc[j];
            g_slot[p] = e * CAP + r;
        } else {
            g_slot[p] = -1;
        }
    }

    if (tid == 0) {
#pragma unroll
        for (int e = 0; e < N_EXP; e++) {
            unsigned u = wsum[31][e >> 1];
            unsigned tot = (e & 1) ? (u >> 16) : (u & 0xFFFFu);
            g_counts[e] = (tot > CAP) ? CAP : (int)tot;
        }
    }
}

// ----------------------------- fp16 prep (vectorized, coalesced) ------------
__global__ void prep_x(const float* __restrict__ x) {
    const int t = blockIdx.x * 256 + threadIdx.x;      // over N_TOK*H/32 blocks
    const float4* src = reinterpret_cast<const float4*>(x) + (size_t)t * 8;
    float v[32];
#pragma unroll
    for (int i = 0; i < 8; i++) {
        float4 f = src[i];
        v[i * 4] = f.x; v[i * 4 + 1] = f.y; v[i * 4 + 2] = f.z; v[i * 4 + 3] = f.w;
    }
    pack32(v, reinterpret_cast<uint4*>(g_Xh) + (size_t)t * 4);
}
// split: blockIdx.y = 0 -> gate rows (2i), 1 -> up rows (2i+1)
__global__ void prep_wgu(const float* __restrict__ Wg, const float* __restrict__ Wu) {
    const int t = blockIdx.x * 256 + threadIdx.x;      // over E*I*(H/32)
    const int kb = t & 63;                              // H/32 = 64
    const int ei = t >> 6;                              // e*I + i
    const int e  = ei / I_DIM;
    const int i  = ei - e * I_DIM;
    const int y  = blockIdx.y;
    const float* W = y ? Wu : Wg;
    const size_t srcb = (size_t)ei * (H_DIM / 4) + kb * 8;
    const size_t dstb = ((size_t)e * 2 * I_DIM + 2 * i + y) * (H_DIM / 8) + kb * 4;
    float v[32];
    const float4* sw = reinterpret_cast<const float4*>(W) + srcb;
#pragma unroll
    for (int q = 0; q < 8; q++) {
        float4 f = sw[q];
        v[q * 4] = f.x; v[q * 4 + 1] = f.y; v[q * 4 + 2] = f.z; v[q * 4 + 3] = f.w;
    }
    pack32(v, reinterpret_cast<uint4*>(g_Wgu) + dstb);
}
__global__ void prep_wd(const float* __restrict__ Wd) {
    const int t = blockIdx.x * 256 + threadIdx.x;      // over E*H*(I/32)
    const int kb  = t % 44;                             // I/32 = 44
    const int row = t / 44;
    const float4* src = reinterpret_cast<const float4*>(Wd) + (size_t)row * (I_DIM / 4) + kb * 8;
    float v[32];
#pragma unroll
    for (int q = 0; q < 8; q++) {
        float4 f = src[q];
        v[q * 4] = f.x; v[q * 4 + 1] = f.y; v[q * 4 + 2] = f.z; v[q * 4 + 3] = f.w;
    }
    pack32(v, reinterpret_cast<uint4*>(g_Wdh) + (size_t)row * (I_DIM / 8) + kb * 4);
}

// ----------------------------- gate+up GEMM + SwiGLU ------------------------
// B tile 256 rows = 128 I-cols, rows 2i/2i+1 = Wg/Wu (prebuilt in g_Wgu).
// 16 warps 4m x 4n, warp tile 32(m) x 64(B-rows). Epilogue staged via smem.
__global__ __launch_bounds__(NTHR, 1)
void gu_kernel() {
    const int e  = blockIdx.z;
    const int m0 = blockIdx.x * 128;
    const int by = blockIdx.y;                   // I block (128 cols)
    const int n0 = by * 128;
    if (m0 >= g_counts[e]) return;

    extern __shared__ char sm[];
    const uint32_t sbase = smem_u32(sm);

    const int tid  = threadIdx.x;
    const int wid  = tid >> 5;
    const int lane = tid & 31;
    const int g    = lane >> 2;
    const int t4   = lane & 3;
    const int wm   = (wid >> 2) * 32;
    const int wn   = (wid & 3) * 64;
    const int gp   = g & 1;                      // row parity of fragment rows

    // loaders: 512 threads; r = tid>>3 (0..63), slice s (16B) of 128B row-chunk
    const int r  = tid >> 3;
    const int s  = tid & 7;
    const int rp = r & 1;                        // parity same for r, r+64, r+128, r+192
    const uint32_t sl = ((s >> 2) ^ rp) * 64 + (s & 3) * 16;  // swizzled 16B slot

    const char* srcA[2]; uint32_t dA[2];
    const char* srcB[4]; uint32_t dB[4];
#pragma unroll
    for (int j = 0; j < 2; j++) {
        int row = r + j * 64;
        srcA[j] = (const char*)(g_Xh + (size_t)g_tokens[e * CAP + m0 + row] * H_DIM) + s * 16;
        dA[j] = (uint32_t)(row * 128) + sl;
    }
#pragma unroll
    for (int j = 0; j < 4; j++) {
        int row = r + j * 64;
        srcB[j] = (const char*)(g_Wgu + ((size_t)e * 2 * I_DIM + (size_t)by * 256 + row) * H_DIM) + s * 16;
        dB[j] = (uint32_t)(B_OFF + row * 128) + sl;
    }

    auto LOAD = [&](int c, int buf) {
        const uint32_t b = sbase + buf * STAGE_B;
        const size_t off = (size_t)c * 128;
#pragma unroll
        for (int j = 0; j < 2; j++) cpa16(b + dA[j], srcA[j] + off);
#pragma unroll
        for (int j = 0; j < 4; j++) cpa16(b + dB[j], srcB[j] + off);
    };

    float acc[2][8][4];
#pragma unroll
    for (int mt = 0; mt < 2; mt++)
#pragma unroll
        for (int nt = 0; nt < 8; nt++)
#pragma unroll
            for (int qq = 0; qq < 4; qq++) acc[mt][nt][qq] = 0.f;

    const int KT = H_DIM / 64;   // 32
    LOAD(0, 0); cpa_commit();
    LOAD(1, 1); cpa_commit();
    LOAD(2, 2); cpa_commit();

#pragma unroll 1
    for (int c = 0; c < KT; c++) {
        cpa_wait2();
        __syncthreads();
        if (c + 3 < KT) LOAD(c + 3, (c + 3) & 3);
        cpa_commit();

        const char* st = sm + (c & 3) * STAGE_B;
#pragma unroll
        for (int ks = 0; ks < 2; ks++) {
            const int col = (ks ^ gp) * 64 + t4 * 16;
            uint4 aLo[2], aHi[2];
#pragma unroll
            for (int mt = 0; mt < 2; mt++) {
                const int row = wm + mt * 16 + g;
                aLo[mt] = *reinterpret_cast<const uint4*>(st + row * 128 + col);
                aHi[mt] = *reinterpret_cast<const uint4*>(st + (row + 8) * 128 + col);
            }
#pragma unroll
            for (int nt = 0; nt < 8; nt++) {
                const int row = wn + nt * 8 + g;
                uint4 bv = *reinterpret_cast<const uint4*>(st + B_OFF + row * 128 + col);
#pragma unroll
                for (int mt = 0; mt < 2; mt++)
                    mma_f16(acc[mt][nt], aLo[mt].x, aHi[mt].x, aLo[mt].y, aHi[mt].y, bv.x, bv.y);
#pragma unroll
                for (int mt = 0; mt < 2; mt++)
                    mma_f16(acc[mt][nt], aLo[mt].z, aHi[mt].z, aLo[mt].w, aHi[mt].w, bv.z, bv.w);
            }
        }
    }

    // ---- epilogue: stage P tile in smem, then coalesced write-out ----
    __syncthreads();
    __half* Ps = reinterpret_cast<__half*>(sm);
    const int PSTR = 136;                        // halves per row (272B stride)
#pragma unroll
    for (int mt = 0; mt < 2; mt++) {
        const int r0 = wm + mt * 16 + g;
#pragma unroll
        for (int nt = 0; nt < 8; nt++) {
            const int ic  = (wn >> 1) + nt * 4 + t4;      // local I col 0..127
            const int pos = (ic & ~31) + perm32(ic & 31); // even for even ic
            float gv0 = acc[mt][nt][0], uv0 = acc[mt][nt][1];
            float v0 = gv0 * uv0 / (1.f + __expf(-gv0));
            float gv1 = acc[mt][nt][2], uv1 = acc[mt][nt][3];
            float v1 = gv1 * uv1 / (1.f + __expf(-gv1));
            uint32_t h0 = (uint32_t)__half_as_ushort(__float2half_rn(v0));
            uint32_t h1 = (uint32_t)__half_as_ushort(__float2half_rn(v1));
            uint32_t p0 = __shfl_xor_sync(0xffffffffu, h0, 1);
            uint32_t p1 = __shfl_xor_sync(0xffffffffu, h1, 1);
            if ((t4 & 1) == 0) {
                *reinterpret_cast<uint32_t*>(&Ps[r0 * PSTR + pos])       = h0 | (p0 << 16);
                *reinterpret_cast<uint32_t*>(&Ps[(r0 + 8) * PSTR + pos]) = h1 | (p1 << 16);
            }
        }
    }
    __syncthreads();
    {
        const int rr = tid >> 2, part = tid & 3;   // 128 rows x 4 segments of 64B
        const uint4* srcp = reinterpret_cast<const uint4*>(Ps + rr * PSTR + part * 32);
        uint4* dstp = reinterpret_cast<uint4*>(
            g_Ph + ((size_t)e * CAP + m0 + rr) * I_DIM + n0 + part * 32);
#pragma unroll
        for (int q = 0; q < 4; q++) dstp[q] = srcp[q];
    }
}

// ----------------------------- down GEMM ------------------------------------
// 128 x 256(H) tile; A = g_Ph (fp16 permuted), B = g_Wdh. 16 warps 4m x 4n.
// Epilogue staged via smem -> coalesced fp16 g_O.
__global__ __launch_bounds__(NTHR, 1)
void down_kernel() {
    const int e  = blockIdx.z;
    const int m0 = blockIdx.x * 128;
    const int n0 = blockIdx.y * 256;
    if (m0 >= g_counts[e]) return;

    extern __shared__ char sm[];
    const uint32_t sbase = smem_u32(sm);

    const int tid  = threadIdx.x;
    const int wid  = tid >> 5;
    const int lane = tid & 31;
    const int g    = lane >> 2;
    const int t4   = lane & 3;
    const int wm   = (wid >> 2) * 32;
    const int wn   = (wid & 3) * 64;
    const int gp   = g & 1;

    const int r  = tid >> 3;
    const int s  = tid & 7;
    const int rp = r & 1;
    const uint32_t sl = ((s >> 2) ^ rp) * 64 + (s & 3) * 16;

    const char* srcA[2]; uint32_t dA[2];
    const char* srcB[4]; uint32_t dB[4];
#pragma unroll
    for (int j = 0; j < 2; j++) {
        int row = r + j * 64;
        srcA[j] = (const char*)(g_Ph + ((size_t)e * CAP + m0 + row) * I_DIM) + s * 16;
        dA[j] = (uint32_t)(row * 128) + sl;
    }
#pragma unroll
    for (int j = 0; j < 4; j++) {
        int row = r + j * 64;
        srcB[j] = (const char*)(g_Wdh + ((size_t)e * H_DIM + n0 + row) * I_DIM) + s * 16;
        dB[j] = (uint32_t)(B_OFF + row * 128) + sl;
    }

    auto LOAD = [&](int c, int buf) {
        const uint32_t b = sbase + buf * STAGE_B;
        const size_t off = (size_t)c * 128;
#pragma unroll
        for (int j = 0; j < 2; j++) cpa16(b + dA[j], srcA[j] + off);
#pragma unroll
        for (int j = 0; j < 4; j++) cpa16(b + dB[j], srcB[j] + off);
    };

    float acc[2][8][4];
#pragma unroll
    for (int mt = 0; mt < 2; mt++)
#pragma unroll
        for (int nt = 0; nt < 8; nt++)
#pragma unroll
            for (int qq = 0; qq < 4; qq++) acc[mt][nt][qq] = 0.f;

    const int KT = I_DIM / 64;   // 22
    LOAD(0, 0); cpa_commit();
    LOAD(1, 1); cpa_commit();
    LOAD(2, 2); cpa_commit();

#pragma unroll 1
    for (int c = 0; c < KT; c++) {
        cpa_wait2();
        __syncthreads();
        if (c + 3 < KT) LOAD(c + 3, (c + 3) & 3);
        cpa_commit();

        const char* st = sm + (c & 3) * STAGE_B;
#pragma unroll
        for (int ks = 0; ks < 2; ks++) {
            const int col = (ks ^ gp) * 64 + t4 * 16;
            uint4 aLo[2], aHi[2];
#pragma unroll
            for (int mt = 0; mt < 2; mt++) {
                const int row = wm + mt * 16 + g;
                aLo[mt] = *reinterpret_cast<const uint4*>(st + row * 128 + col);
                aHi[mt] = *reinterpret_cast<const uint4*>(st + (row + 8) * 128 + col);
            }
#pragma unroll
            for (int nt = 0; nt < 8; nt++) {
                const int row = wn + nt * 8 + g;
                uint4 bv = *reinterpret_cast<const uint4*>(st + B_OFF + row * 128 + col);
#pragma unroll
                for (int mt = 0; mt < 2; mt++)
                    mma_f16(acc[mt][nt], aLo[mt].x, aHi[mt].x, aLo[mt].y, aHi[mt].y, bv.x, bv.y);
#pragma unroll
                for (int mt = 0; mt < 2; mt++)
                    mma_f16(acc[mt][nt], aLo[mt].z, aHi[mt].z, aLo[mt].w, aHi[mt].w, bv.z, bv.w);
            }
        }
    }

    // ---- epilogue: stage O tile (128x256 fp16) in smem, coalesced write ----
    __syncthreads();
    __half* Os = reinterpret_cast<__half*>(sm);
    const int OSTR = 264;                        // halves per row (528B stride)
#pragma unroll
    for (int mt = 0; mt < 2; mt++) {
        const int r0 = wm + mt * 16 + g;
#pragma unroll
        for (int nt = 0; nt < 8; nt++) {
            const int cc = wn + nt * 8 + t4 * 2;
            *reinterpret_cast<__half2*>(&Os[r0 * OSTR + cc]) =
                __floats2half2_rn(acc[mt][nt][0], acc[mt][nt][1]);
            *reinterpret_cast<__half2*>(&Os[(r0 + 8) * OSTR + cc]) =
                __floats2half2_rn(acc[mt][nt][2], acc[mt][nt][3]);
        }
    }
    __syncthreads();
    {
        const int rr = tid & 127, part = tid >> 7;   // 128 rows x 4 segments of 128B
        const uint4* srcp = reinterpret_cast<const uint4*>(Os + rr * OSTR + part * 64);
        uint4* dstp = reinterpret_cast<uint4*>(
            g_O + ((size_t)e * CAP + m0 + rr) * H_DIM + n0 + part * 64);
#pragma unroll
        for (int q = 0; q < 8; q++) dstp[q] = srcp[q];
    }
}

// ----------------------------- combine --------------------------------------
__global__ void combine_kernel(float* __restrict__ out) {
    const int idx = blockIdx.x * 512 + threadIdx.x;  // over N_TOK * H_DIM/4
    const int n  = idx >> 9;                         // H_DIM/4 = 512
    const int c2 = (idx & 511) * 2;                  // half2 index within row
    const int s0 = g_slot[n];
    const int s1 = g_slot[N_TOK + n];
    float4 acc = make_float4(0.f, 0.f, 0.f, 0.f);
    const __half2* O2 = reinterpret_cast<const __half2*>(g_O);
    if (s0 >= 0) {
        float w = g_wts[s0];
        float2 a = __half22float2(O2[(size_t)s0 * (H_DIM / 2) + c2]);
        float2 b = __half22float2(O2[(size_t)s0 * (H_DIM / 2) + c2 + 1]);
        acc.x += w * a.x; acc.y += w * a.y; acc.z += w * b.x; acc.w += w * b.y;
    }
    if (s1 >= 0) {
        float w = g_wts[s1];
        float2 a = __half22float2(O2[(size_t)s1 * (H_DIM / 2) + c2]);
        float2 b = __half22float2(O2[(size_t)s1 * (H_DIM / 2) + c2 + 1]);
        acc.x += w * a.x; acc.y += w * a.y; acc.z += w * b.x; acc.w += w * b.y;
    }
    reinterpret_cast<float4*>(out)[idx] = acc;
}

// ----------------------------- launch --------------------------------------
#define DYN_SMEM (NSTAGE * STAGE_B)   // 196608 bytes

extern "C" void kernel_launch(void* const* d_in, const int* in_sizes, int n_in,
                              void* d_out, int out_size) {
    const float* x  = (const float*)d_in[0];
    const float* Wr = (const float*)d_in[1];
    const float* Wg = (const float*)d_in[2];
    const float* Wu = (const float*)d_in[3];
    const float* Wd = (const float*)d_in[4];
    float* out = (float*)d_out;
    (void)in_sizes; (void)n_in; (void)out_size;

    // side streams + events for fork-join graph (host resources, created once)
    static cudaStream_t s1 = nullptr, s2 = nullptr;
    static cudaEvent_t evr = nullptr, ev1 = nullptr, ev2 = nullptr, evx = nullptr;
    if (s1 == nullptr) {
        cudaStreamCreateWithFlags(&s1, cudaStreamNonBlocking);
        cudaStreamCreateWithFlags(&s2, cudaStreamNonBlocking);
        cudaEventCreateWithFlags(&evr, cudaEventDisableTiming);
        cudaEventCreateWithFlags(&ev1, cudaEventDisableTiming);
        cudaEventCreateWithFlags(&ev2, cudaEventDisableTiming);
        cudaEventCreateWithFlags(&evx, cudaEventDisableTiming);
    }
    cudaFuncSetAttribute(gu_kernel,   cudaFuncAttributeMaxDynamicSharedMemorySize, DYN_SMEM);
    cudaFuncSetAttribute(down_kernel, cudaFuncAttributeMaxDynamicSharedMemorySize, DYN_SMEM);

    // fork
    cudaEventRecord(evr, 0);
    cudaStreamWaitEvent(s1, evr, 0);
    cudaStreamWaitEvent(s2, evr, 0);

    // chain A (main stream): routing
    router_kernel<<<N_TOK / 8, 256>>>(x, Wr);
    sched_kernel<<<1, 1024>>>();

    // chain B (s1): gate/up weights only (critical path to gu)
    dim3 wgrid((N_EXP * I_DIM * (H_DIM / 32)) / 256, 2);
    prep_wgu<<<wgrid, 256, 0, s1>>>(Wg, Wu);
    cudaEventRecord(ev1, s1);

    // chain C (s2): activations first (gu needs them), then down weights
    prep_x  <<<(N_TOK * H_DIM / 32) / 256, 256, 0, s2>>>(x);
    cudaEventRecord(evx, s2);
    prep_wd <<<(N_EXP * H_DIM * (I_DIM / 32)) / 256, 256, 0, s2>>>(Wd);
    cudaEventRecord(ev2, s2);

    // join (wgu, x) -> gu
    cudaStreamWaitEvent(0, ev1, 0);
    cudaStreamWaitEvent(0, evx, 0);
    dim3 ggrid(CAP / 128, I_DIM / 128, N_EXP);   // (10, 11, 8), m fastest for L2 reuse
    gu_kernel<<<ggrid, NTHR, DYN_SMEM>>>();

    // join wd -> down (prep_wd hides under gu)
    cudaStreamWaitEvent(0, ev2, 0);
    dim3 dgrid(CAP / 128, H_DIM / 256, N_EXP);   // (10, 8, 8)
    down_kernel<<<dgrid, NTHR, DYN_SMEM>>>();

    combine_kernel<<<(N_TOK * (H_DIM / 4)) / 512, 512>>>(out);
}